// round 2
// baseline (speedup 1.0000x reference)
#include <cuda_runtime.h>
#include <cuda_bf16.h>
#include <cstdint>
#include <cstddef>

// ---------------------------------------------------------------------------
// Problem constants
// ---------------------------------------------------------------------------
#define HIDN   512
#define BATCH  64
#define SEQT   256
#define MTOT   (BATCH * SEQT)       // 16384
#define G4     (4 * HIDN)           // 2048
#define NCLS   50257

// ---------------------------------------------------------------------------
// Static device scratch (no cudaMalloc allowed anywhere)
// ---------------------------------------------------------------------------
__device__ float d_xg[(size_t)MTOT * G4];                 // 134 MB, reused per layer
__device__ float d_hseq0[(size_t)(SEQT + 1) * BATCH * HIDN]; // block 0 = zeros
__device__ float d_hseq1[(size_t)(SEQT + 1) * BATCH * HIDN];
__device__ float d_c0[(size_t)BATCH * HIDN];
__device__ float d_c1[(size_t)BATCH * HIDN];

// ---------------------------------------------------------------------------
// Zero-init kernel (h_0 blocks and cell states) — re-run every launch
// ---------------------------------------------------------------------------
__global__ void zero_init(float* a, float* b, float* c, float* d, int n)
{
    for (int i = blockIdx.x * blockDim.x + threadIdx.x; i < n;
         i += gridDim.x * blockDim.x) {
        a[i] = 0.0f; b[i] = 0.0f; c[i] = 0.0f; d[i] = 0.0f;
    }
}

// ---------------------------------------------------------------------------
// GEMM: C[m][n] = sum_k A'[m][k] * B[n][k] + bias1[n] (+ bias2[n])
//   A' = A with optional row gather (embedding): row m -> emb[gX[(m%64)*256 + m/64]]
//   Block tile 64(m) x 128(n), 256 threads, thread tile 4x8, K chunk 16.
//   Requires: M multiple of 64, K multiple of 16. N arbitrary (guarded).
// ---------------------------------------------------------------------------
__global__ __launch_bounds__(256)
void gemm_tk(const float* __restrict__ A, const float* __restrict__ B,
             float* __restrict__ C,
             const float* __restrict__ bias1, const float* __restrict__ bias2,
             const int* __restrict__ gX,
             int M, int N, int K)
{
    __shared__ float As[16][64];
    __shared__ float Bs[16][132];

    const int tid = threadIdx.x;
    const int m0  = blockIdx.y * 64;
    const int n0  = blockIdx.x * 128;

    // ---- A loader mapping: one float4 per thread per chunk -------------
    const int arow_l = tid >> 2;          // 0..63 (local row)
    const int akq    = (tid & 3) * 4;     // 0,4,8,12
    const float* Aptr;
    {
        int arow = m0 + arow_l;
        if (gX) {
            int bb = arow & 63;
            int tt = arow >> 6;
            Aptr = A + (size_t)gX[bb * SEQT + tt] * K + akq;
        } else {
            Aptr = A + (size_t)arow * K + akq;
        }
    }

    // ---- B loader mapping: two float4 per thread per chunk -------------
    const float* Bp[2];
    int  nlB[2], kqB[2], bval[2];
#pragma unroll
    for (int i = 0; i < 2; i++) {
        int idx = tid + i * 256;          // 0..511
        int nl  = idx >> 2;               // 0..127
        int kq  = (idx & 3) * 4;
        nlB[i]  = nl;
        kqB[i]  = kq;
        bval[i] = (n0 + nl) < N;
        Bp[i]   = B + (size_t)(bval[i] ? (n0 + nl) : 0) * K + kq;
    }

    // ---- compute mapping ------------------------------------------------
    const int warp = tid >> 5;
    const int lane = tid & 31;
    const int wm = warp >> 2;             // 0..1
    const int wn = warp & 3;              // 0..3
    const int lm = lane >> 2;             // 0..7
    const int ln = lane & 3;              // 0..3
    const int rm = wm * 32 + lm * 4;      // 0..60
    const int rn = wn * 32 + ln * 8;      // 0..120

    float acc[4][8];
#pragma unroll
    for (int i = 0; i < 4; i++)
#pragma unroll
        for (int j = 0; j < 8; j++) acc[i][j] = 0.0f;

    for (int k0 = 0; k0 < K; k0 += 16) {
        // global loads into registers
        float4 av = *reinterpret_cast<const float4*>(Aptr + k0);
        float4 bv[2];
#pragma unroll
        for (int i = 0; i < 2; i++) {
            if (bval[i]) bv[i] = *reinterpret_cast<const float4*>(Bp[i] + k0);
            else         bv[i] = make_float4(0.f, 0.f, 0.f, 0.f);
        }

        __syncthreads();  // previous chunk's compute done

        As[akq + 0][arow_l] = av.x;
        As[akq + 1][arow_l] = av.y;
        As[akq + 2][arow_l] = av.z;
        As[akq + 3][arow_l] = av.w;
#pragma unroll
        for (int i = 0; i < 2; i++) {
            Bs[kqB[i] + 0][nlB[i]] = bv[i].x;
            Bs[kqB[i] + 1][nlB[i]] = bv[i].y;
            Bs[kqB[i] + 2][nlB[i]] = bv[i].z;
            Bs[kqB[i] + 3][nlB[i]] = bv[i].w;
        }

        __syncthreads();  // smem ready

#pragma unroll
        for (int kk = 0; kk < 16; kk++) {
            float a4[4], b8[8];
            *reinterpret_cast<float4*>(a4)     = *reinterpret_cast<const float4*>(&As[kk][rm]);
            *reinterpret_cast<float4*>(b8)     = *reinterpret_cast<const float4*>(&Bs[kk][rn]);
            *reinterpret_cast<float4*>(b8 + 4) = *reinterpret_cast<const float4*>(&Bs[kk][rn + 4]);
#pragma unroll
            for (int i = 0; i < 4; i++)
#pragma unroll
                for (int j = 0; j < 8; j++)
                    acc[i][j] += a4[i] * b8[j];
        }
    }

    // ---- epilogue --------------------------------------------------------
#pragma unroll
    for (int j = 0; j < 8; j++) {
        int n = n0 + rn + j;
        if (n < N) {
            float bsum = bias1[n] + (bias2 ? bias2[n] : 0.0f);
#pragma unroll
            for (int i = 0; i < 4; i++) {
                C[(size_t)(m0 + rm + i) * N + n] = acc[i][j] + bsum;
            }
        }
    }
}

// ---------------------------------------------------------------------------
// LSTM step: one launch per timestep.
//   g = xg_t + h_prev @ w_hh^T; gates i,f,g,o; c,h update.
//   Grid 128 blocks x 256 threads. Block b owns hidden units [b*4, b*4+4),
//   i.e. 16 gate rows: q*512 + b*4 + j for q in 0..3, j in 0..3.
//   h_prev staged transposed in SMEM: h_sT[k][batch]  (512 x 64 floats).
// ---------------------------------------------------------------------------
__device__ __forceinline__ float sigm_f(float x)
{
    return 1.0f / (1.0f + __expf(-x));
}

__global__ __launch_bounds__(256)
void lstm_step(const float* __restrict__ xg_t,   // [64][2048] for this t
               const float* __restrict__ hprev,  // [64][512]
               float* __restrict__ hout,         // [64][512]
               float* __restrict__ c,            // [64][512]
               const float* __restrict__ w_hh)   // [2048][512]
{
    extern __shared__ float sm[];
    float* h_sT = sm;              // 512*64 floats
    float* g_s  = sm + 512 * 64;   // 16*64 floats

    const int tid = threadIdx.x;
    const int blk = blockIdx.x;    // 0..127

    // ---- stage h transposed: h_sT[k*64 + b] = hprev[b*512 + k] ----------
#pragma unroll
    for (int i = 0; i < 32; i++) {
        int idx = tid + i * 256;   // 0..8191 (float4 units)
        int b   = idx & 63;
        int k4  = idx >> 6;        // 0..127
        float4 v = *reinterpret_cast<const float4*>(hprev + b * 512 + k4 * 4);
        int base = (k4 * 4) * 64 + b;
        h_sT[base]       = v.x;
        h_sT[base + 64]  = v.y;
        h_sT[base + 128] = v.z;
        h_sT[base + 192] = v.w;
    }
    __syncthreads();

    // ---- matmul: 2 rows x 2 batches per thread ---------------------------
    const int rp  = tid >> 5;      // 0..7
    const int bp  = tid & 31;      // batches bp, bp+32
    const int lr0 = rp * 2;
    const int lr1 = rp * 2 + 1;
    const int grow0 = (lr0 >> 2) * 512 + blk * 4 + (lr0 & 3);
    const int grow1 = (lr1 >> 2) * 512 + blk * 4 + (lr1 & 3);
    const float* w0 = w_hh + (size_t)grow0 * 512;
    const float* w1 = w_hh + (size_t)grow1 * 512;
    const int b0 = bp, b1 = bp + 32;

    float a00 = 0.f, a01 = 0.f, a10 = 0.f, a11 = 0.f;
#pragma unroll 4
    for (int k = 0; k < 512; k += 4) {
        float4 wa = *reinterpret_cast<const float4*>(w0 + k);
        float4 wb = *reinterpret_cast<const float4*>(w1 + k);
        const float* hk = h_sT + k * 64;
        float h00 = hk[b0],       h01 = hk[b1];
        float h10 = hk[64 + b0],  h11 = hk[64 + b1];
        float h20 = hk[128 + b0], h21 = hk[128 + b1];
        float h30 = hk[192 + b0], h31 = hk[192 + b1];
        a00 += wa.x * h00; a00 += wa.y * h10; a00 += wa.z * h20; a00 += wa.w * h30;
        a01 += wa.x * h01; a01 += wa.y * h11; a01 += wa.z * h21; a01 += wa.w * h31;
        a10 += wb.x * h00; a10 += wb.y * h10; a10 += wb.z * h20; a10 += wb.w * h30;
        a11 += wb.x * h01; a11 += wb.y * h11; a11 += wb.z * h21; a11 += wb.w * h31;
    }

    g_s[lr0 * 64 + b0] = a00;
    g_s[lr0 * 64 + b1] = a01;
    g_s[lr1 * 64 + b0] = a10;
    g_s[lr1 * 64 + b1] = a11;
    __syncthreads();

    // ---- gates + cell update: thread = (j 0..3, batch 0..63) -------------
    const int j = tid >> 6;
    const int b = tid & 63;
    const int unit = blk * 4 + j;
    const float* xgb = xg_t + (size_t)b * G4;

    float gi = g_s[(0 * 4 + j) * 64 + b] + xgb[unit];
    float gf = g_s[(1 * 4 + j) * 64 + b] + xgb[512 + unit];
    float gg = g_s[(2 * 4 + j) * 64 + b] + xgb[1024 + unit];
    float go = g_s[(3 * 4 + j) * 64 + b] + xgb[1536 + unit];

    float i_t = sigm_f(gi);
    float f_t = sigm_f(gf);
    float g_t = tanhf(gg);
    float o_t = sigm_f(go);

    float cn = f_t * c[b * 512 + unit] + i_t * g_t;
    c[b * 512 + unit]    = cn;
    hout[b * 512 + unit] = o_t * tanhf(cn);
}

// ---------------------------------------------------------------------------
// kernel_launch
// ---------------------------------------------------------------------------
extern "C" void kernel_launch(void* const* d_in, const int* in_sizes, int n_in,
                              void* d_out, int out_size)
{
    const int*   X     = (const int*)  d_in[0];
    const float* emb   = (const float*)d_in[1];
    const float* w_ih0 = (const float*)d_in[2];
    const float* w_hh0 = (const float*)d_in[3];
    const float* b_ih0 = (const float*)d_in[4];
    const float* b_hh0 = (const float*)d_in[5];
    const float* w_ih1 = (const float*)d_in[6];
    const float* w_hh1 = (const float*)d_in[7];
    const float* b_ih1 = (const float*)d_in[8];
    const float* b_hh1 = (const float*)d_in[9];
    const float* Wout  = (const float*)d_in[10];
    const float* bout  = (const float*)d_in[11];
    float* out = (float*)d_out;

    float *xg, *hs0, *hs1, *c0, *c1;
    cudaGetSymbolAddress((void**)&xg,  d_xg);
    cudaGetSymbolAddress((void**)&hs0, d_hseq0);
    cudaGetSymbolAddress((void**)&hs1, d_hseq1);
    cudaGetSymbolAddress((void**)&c0,  d_c0);
    cudaGetSymbolAddress((void**)&c1,  d_c1);

    const int step_smem = (512 * 64 + 16 * 64) * sizeof(float); // 135168 B
    static bool attr_set = false;
    if (!attr_set) {
        cudaFuncSetAttribute(lstm_step,
                             cudaFuncAttributeMaxDynamicSharedMemorySize,
                             step_smem);
        attr_set = true;
    }

    // 1) zero h_0 blocks and cell states
    zero_init<<<64, 256>>>(hs0, hs1, c0, c1, BATCH * HIDN);

    // 2) xg for layer 0 (embedding gather fused)
    {
        dim3 grid(G4 / 128, MTOT / 64);
        gemm_tk<<<grid, 256>>>(emb, w_ih0, xg, b_ih0, b_hh0, X,
                               MTOT, G4, HIDN);
    }

    // 3) layer-0 recurrence
    for (int t = 0; t < SEQT; t++) {
        lstm_step<<<128, 256, step_smem>>>(
            xg  + (size_t)t * BATCH * G4,
            hs0 + (size_t)t * BATCH * HIDN,
            hs0 + (size_t)(t + 1) * BATCH * HIDN,
            c0, w_hh0);
    }

    // 4) xg for layer 1 (A = layer-0 hidden sequence, offset past zero block)
    {
        dim3 grid(G4 / 128, MTOT / 64);
        gemm_tk<<<grid, 256>>>(hs0 + (size_t)BATCH * HIDN, w_ih1, xg,
                               b_ih1, b_hh1, nullptr,
                               MTOT, G4, HIDN);
    }

    // 5) layer-1 recurrence
    for (int t = 0; t < SEQT; t++) {
        lstm_step<<<128, 256, step_smem>>>(
            xg  + (size_t)t * BATCH * G4,
            hs1 + (size_t)t * BATCH * HIDN,
            hs1 + (size_t)(t + 1) * BATCH * HIDN,
            c1, w_hh1);
    }

    // 6) logits = h_last @ W^T + b
    {
        dim3 grid((NCLS + 127) / 128, BATCH / 64);
        gemm_tk<<<grid, 256>>>(hs1 + (size_t)SEQT * BATCH * HIDN, Wout, out,
                               bout, nullptr, nullptr,
                               BATCH, NCLS, HIDN);
    }
}

// round 3
// speedup vs baseline: 2.2386x; 2.2386x over previous
#include <cuda_runtime.h>
#include <cuda_bf16.h>
#include <cstdint>
#include <cstddef>

// ---------------------------------------------------------------------------
// Problem constants
// ---------------------------------------------------------------------------
#define HIDN   512
#define BATCH  64
#define SEQT   256
#define MTOT   (BATCH * SEQT)       // 16384
#define G4     (4 * HIDN)           // 2048
#define NCLS   50257

// ---------------------------------------------------------------------------
// Static device scratch (no cudaMalloc allowed anywhere)
// ---------------------------------------------------------------------------
__device__ float d_xg[(size_t)MTOT * G4];                    // gate pre-activations
__device__ float d_hseq0[(size_t)(SEQT + 1) * BATCH * HIDN]; // slot 0 = zeros
__device__ float d_hseq1[(size_t)(SEQT + 1) * BATCH * HIDN];
__device__ unsigned d_barrier;

// ---------------------------------------------------------------------------
// Init kernels
// ---------------------------------------------------------------------------
__global__ void zero_init(float* a, float* b, int n)
{
    for (int i = blockIdx.x * blockDim.x + threadIdx.x; i < n;
         i += gridDim.x * blockDim.x) {
        a[i] = 0.0f; b[i] = 0.0f;
    }
}

__global__ void zero_bar()
{
    if (threadIdx.x == 0) d_barrier = 0;
}

// ---------------------------------------------------------------------------
// Bulk fp32 GEMM (unchanged from round 1): C[m][n] = sum_k A'[m][k]*B[n][k]
// + bias1[n] (+ bias2[n]); optional embedding row gather.
// Block tile 64(m) x 128(n), 256 threads, thread tile 4x8, K chunk 16.
// ---------------------------------------------------------------------------
__global__ __launch_bounds__(256)
void gemm_tk(const float* __restrict__ A, const float* __restrict__ B,
             float* __restrict__ C,
             const float* __restrict__ bias1, const float* __restrict__ bias2,
             const int* __restrict__ gX,
             int M, int N, int K)
{
    __shared__ float As[16][64];
    __shared__ float Bs[16][132];

    const int tid = threadIdx.x;
    const int m0  = blockIdx.y * 64;
    const int n0  = blockIdx.x * 128;

    const int arow_l = tid >> 2;
    const int akq    = (tid & 3) * 4;
    const float* Aptr;
    {
        int arow = m0 + arow_l;
        if (gX) {
            int bb = arow & 63;
            int tt = arow >> 6;
            Aptr = A + (size_t)gX[bb * SEQT + tt] * K + akq;
        } else {
            Aptr = A + (size_t)arow * K + akq;
        }
    }

    const float* Bp[2];
    int  nlB[2], kqB[2], bval[2];
#pragma unroll
    for (int i = 0; i < 2; i++) {
        int idx = tid + i * 256;
        int nl  = idx >> 2;
        int kq  = (idx & 3) * 4;
        nlB[i]  = nl;
        kqB[i]  = kq;
        bval[i] = (n0 + nl) < N;
        Bp[i]   = B + (size_t)(bval[i] ? (n0 + nl) : 0) * K + kq;
    }

    const int warp = tid >> 5;
    const int lane = tid & 31;
    const int wm = warp >> 2;
    const int wn = warp & 3;
    const int lm = lane >> 2;
    const int ln = lane & 3;
    const int rm = wm * 32 + lm * 4;
    const int rn = wn * 32 + ln * 8;

    float acc[4][8];
#pragma unroll
    for (int i = 0; i < 4; i++)
#pragma unroll
        for (int j = 0; j < 8; j++) acc[i][j] = 0.0f;

    for (int k0 = 0; k0 < K; k0 += 16) {
        float4 av = *reinterpret_cast<const float4*>(Aptr + k0);
        float4 bv[2];
#pragma unroll
        for (int i = 0; i < 2; i++) {
            if (bval[i]) bv[i] = *reinterpret_cast<const float4*>(Bp[i] + k0);
            else         bv[i] = make_float4(0.f, 0.f, 0.f, 0.f);
        }

        __syncthreads();

        As[akq + 0][arow_l] = av.x;
        As[akq + 1][arow_l] = av.y;
        As[akq + 2][arow_l] = av.z;
        As[akq + 3][arow_l] = av.w;
#pragma unroll
        for (int i = 0; i < 2; i++) {
            Bs[kqB[i] + 0][nlB[i]] = bv[i].x;
            Bs[kqB[i] + 1][nlB[i]] = bv[i].y;
            Bs[kqB[i] + 2][nlB[i]] = bv[i].z;
            Bs[kqB[i] + 3][nlB[i]] = bv[i].w;
        }

        __syncthreads();

#pragma unroll
        for (int kk = 0; kk < 16; kk++) {
            float a4[4], b8[8];
            *reinterpret_cast<float4*>(a4)     = *reinterpret_cast<const float4*>(&As[kk][rm]);
            *reinterpret_cast<float4*>(b8)     = *reinterpret_cast<const float4*>(&Bs[kk][rn]);
            *reinterpret_cast<float4*>(b8 + 4) = *reinterpret_cast<const float4*>(&Bs[kk][rn + 4]);
#pragma unroll
            for (int i = 0; i < 4; i++)
#pragma unroll
                for (int j = 0; j < 8; j++)
                    acc[i][j] += a4[i] * b8[j];
        }
    }

#pragma unroll
    for (int j = 0; j < 8; j++) {
        int n = n0 + rn + j;
        if (n < N) {
            float bsum = bias1[n] + (bias2 ? bias2[n] : 0.0f);
#pragma unroll
            for (int i = 0; i < 4; i++) {
                C[(size_t)(m0 + rm + i) * N + n] = acc[i][j] + bsum;
            }
        }
    }
}

// ---------------------------------------------------------------------------
// Persistent LSTM layer kernel (tensor cores, tf32)
//
// Grid: 64 blocks x 256 threads. Block blk owns hidden units
//   [blk*8, blk*8+8) -> 32 gate columns: rows w_hh[q*512 + blk*8 + j].
// SMEM: w tile (32x512 tf32, stride 516) resident across all 256 steps,
//       h tile (64x512, stride 516) restaged per step,
//       c state (8x64, stride 68) resident,
//       g staging (32x.., stride 65) aliased onto h tile (dead after k-loop).
// Per step: stage h -> mma k-loop (m16n8k8 tf32) -> gates+cell in SMEM ->
//           write tf32-rounded h to hseq[t+1] -> global spin barrier.
// ---------------------------------------------------------------------------
#define HS_STRIDE 516
#define CS_STRIDE 68
#define GS_STRIDE 65
#define WS_OFF    (64 * HS_STRIDE)           // 33024 floats
#define CS_OFF    (WS_OFF + 32 * HS_STRIDE)  // 49536 floats
#define SMEM_FLOATS (CS_OFF + 8 * CS_STRIDE) // 50080 floats
#define SMEM_BYTES  (SMEM_FLOATS * 4)        // 200320 B

__device__ __forceinline__ unsigned f2tf(float f)
{
    unsigned u;
    asm("cvt.rna.tf32.f32 %0, %1;" : "=r"(u) : "f"(f));
    return u;
}

__device__ __forceinline__ void mma_tf32(float* c, unsigned a0, unsigned a1,
                                         unsigned a2, unsigned a3,
                                         unsigned b0, unsigned b1)
{
    asm volatile(
        "mma.sync.aligned.m16n8k8.row.col.f32.tf32.tf32.f32 "
        "{%0,%1,%2,%3}, {%4,%5,%6,%7}, {%8,%9}, {%0,%1,%2,%3};\n"
        : "+f"(c[0]), "+f"(c[1]), "+f"(c[2]), "+f"(c[3])
        : "r"(a0), "r"(a1), "r"(a2), "r"(a3), "r"(b0), "r"(b1));
}

__device__ __forceinline__ float sigm_f(float x)
{
    return 1.0f / (1.0f + __expf(-x));
}

__global__ __launch_bounds__(256)
void lstm_layer(const float* __restrict__ xg,     // [256][64][2048]
                float* __restrict__ hseq,         // [257][64][512], slot0 = 0
                const float* __restrict__ w_hh)   // [2048][512]
{
    extern __shared__ float sm[];
    float* h_s = sm;                 // 64 x 512, stride 516
    float* w_s = sm + WS_OFF;        // 32 x 512, stride 516
    float* c_s = sm + CS_OFF;        // 8 x 64, stride 68
    float* g_s = sm;                 // alias of h_s (32 x 64, stride 65)

    const int tid  = threadIdx.x;
    const int blk  = blockIdx.x;     // 0..63
    const int lane = tid & 31;
    const int warp = tid >> 5;
    const int wm   = warp >> 1;      // 0..3  (batch 16-row tile)
    const int wn   = warp & 1;       // 0..1  (gate pair)
    const int gid  = lane >> 2;      // 0..7
    const int tig  = lane & 3;       // 0..3

    // ---- preload w tile as tf32 (once) -----------------------------------
    // local row r: gate q = r>>3, unit j = r&7 -> w_hh row q*512 + blk*8 + j
#pragma unroll
    for (int i = 0; i < 16; i++) {
        int idx = tid + i * 256;     // 0..4095 float4 slots
        int r   = idx >> 7;          // 0..31
        int q4  = (idx & 127) * 4;   // k offset
        int grow = (r >> 3) * 512 + blk * 8 + (r & 7);
        float4 v = *reinterpret_cast<const float4*>(w_hh + (size_t)grow * 512 + q4);
        unsigned* dst = reinterpret_cast<unsigned*>(w_s + r * HS_STRIDE + q4);
        dst[0] = f2tf(v.x); dst[1] = f2tf(v.y);
        dst[2] = f2tf(v.z); dst[3] = f2tf(v.w);
    }
    // zero cell state
    for (int i = tid; i < 8 * CS_STRIDE; i += 256) c_s[i] = 0.0f;
    __syncthreads();

    // fragment base pointers (h staged per step; w fixed)
    const float* pb0 = w_s + ((wn * 2 + 0) * 8 + gid) * HS_STRIDE + tig;
    const float* pb1 = w_s + ((wn * 2 + 1) * 8 + gid) * HS_STRIDE + tig;
    const float* pa  = h_s + (wm * 16 + gid) * HS_STRIDE + tig;
    const float* pa8 = pa + 8 * HS_STRIDE;

    // gate-phase mapping: pairs p = tid, tid+256 -> (b = p>>3, ul = p&7)
    const int gb0 = tid >> 3;
    const int gul = tid & 7;
    const int ucol = blk * 8 + gul;

    for (int t = 0; t < SEQT; t++) {
        // ---- stage h_{t} into SMEM (tf32 bits already) --------------------
        const float* hp = hseq + (size_t)t * (BATCH * HIDN);
#pragma unroll
        for (int i = 0; i < 32; i++) {
            int idx = tid + i * 256;     // 0..8191
            int b   = idx >> 7;          // 0..63
            int q4  = (idx & 127) * 4;
            float4 v = *reinterpret_cast<const float4*>(hp + b * 512 + q4);
            *reinterpret_cast<float4*>(h_s + b * HS_STRIDE + q4) = v;
        }
        __syncthreads();

        // ---- k-loop: 64 x m16n8k8 tf32 mma per warp per gate tile --------
        float acc0[4] = {0.f, 0.f, 0.f, 0.f};
        float acc1[4] = {0.f, 0.f, 0.f, 0.f};
#pragma unroll 4
        for (int k0 = 0; k0 < 512; k0 += 8) {
            unsigned a0 = __float_as_uint(pa [k0]);
            unsigned a1 = __float_as_uint(pa8[k0]);
            unsigned a2 = __float_as_uint(pa [k0 + 4]);
            unsigned a3 = __float_as_uint(pa8[k0 + 4]);
            unsigned b00 = __float_as_uint(pb0[k0]);
            unsigned b01 = __float_as_uint(pb0[k0 + 4]);
            unsigned b10 = __float_as_uint(pb1[k0]);
            unsigned b11 = __float_as_uint(pb1[k0 + 4]);
            mma_tf32(acc0, a0, a1, a2, a3, b00, b01);
            mma_tf32(acc1, a0, a1, a2, a3, b10, b11);
        }
        __syncthreads();   // h_s dead; g_s alias may be written now

        // ---- stage C frags to g_s[32 rows (q*8+ul)][64 b], stride 65 -----
        {
            int b  = wm * 16 + gid;
            int g0 = wn * 2 + 0;
            int g1 = wn * 2 + 1;
            int u0 = 2 * tig;
            g_s[(g0 * 8 + u0    ) * GS_STRIDE + b    ] = acc0[0];
            g_s[(g0 * 8 + u0 + 1) * GS_STRIDE + b    ] = acc0[1];
            g_s[(g0 * 8 + u0    ) * GS_STRIDE + b + 8] = acc0[2];
            g_s[(g0 * 8 + u0 + 1) * GS_STRIDE + b + 8] = acc0[3];
            g_s[(g1 * 8 + u0    ) * GS_STRIDE + b    ] = acc1[0];
            g_s[(g1 * 8 + u0 + 1) * GS_STRIDE + b    ] = acc1[1];
            g_s[(g1 * 8 + u0    ) * GS_STRIDE + b + 8] = acc1[2];
            g_s[(g1 * 8 + u0 + 1) * GS_STRIDE + b + 8] = acc1[3];
        }
        __syncthreads();

        // ---- gates + cell update: 2 (b, u) pairs per thread ----------------
        const float* xgt = xg + (size_t)t * (BATCH * G4);
        float* hout = hseq + (size_t)(t + 1) * (BATCH * HIDN);
#pragma unroll
        for (int pp = 0; pp < 2; pp++) {
            int b  = gb0 + pp * 32;
            const float* xgb = xgt + (size_t)b * G4;
            float gi = g_s[( 0 + gul) * GS_STRIDE + b] + xgb[ucol];
            float gf = g_s[( 8 + gul) * GS_STRIDE + b] + xgb[512  + ucol];
            float gg = g_s[(16 + gul) * GS_STRIDE + b] + xgb[1024 + ucol];
            float go = g_s[(24 + gul) * GS_STRIDE + b] + xgb[1536 + ucol];

            float i_t = sigm_f(gi);
            float f_t = sigm_f(gf);
            float g_t = tanhf(gg);
            float o_t = sigm_f(go);

            float cn = f_t * c_s[gul * CS_STRIDE + b] + i_t * g_t;
            c_s[gul * CS_STRIDE + b] = cn;
            float hv = o_t * tanhf(cn);
            hout[b * 512 + ucol] = __uint_as_float(f2tf(hv));
        }
        __syncthreads();

        // ---- grid barrier --------------------------------------------------
        if (tid == 0) {
            unsigned* bar = &d_barrier;
            asm volatile("red.release.gpu.global.add.u32 [%0], %1;"
                         :: "l"(bar), "r"(1u) : "memory");
            unsigned target = 64u * (unsigned)(t + 1);
            unsigned v;
            do {
                asm volatile("ld.acquire.gpu.global.u32 %0, [%1];"
                             : "=r"(v) : "l"(bar) : "memory");
            } while (v < target);
        }
        __syncthreads();
    }
}

// ---------------------------------------------------------------------------
// kernel_launch
// ---------------------------------------------------------------------------
extern "C" void kernel_launch(void* const* d_in, const int* in_sizes, int n_in,
                              void* d_out, int out_size)
{
    const int*   X     = (const int*)  d_in[0];
    const float* emb   = (const float*)d_in[1];
    const float* w_ih0 = (const float*)d_in[2];
    const float* w_hh0 = (const float*)d_in[3];
    const float* b_ih0 = (const float*)d_in[4];
    const float* b_hh0 = (const float*)d_in[5];
    const float* w_ih1 = (const float*)d_in[6];
    const float* w_hh1 = (const float*)d_in[7];
    const float* b_ih1 = (const float*)d_in[8];
    const float* b_hh1 = (const float*)d_in[9];
    const float* Wout  = (const float*)d_in[10];
    const float* bout  = (const float*)d_in[11];
    float* out = (float*)d_out;

    float *xg, *hs0, *hs1;
    cudaGetSymbolAddress((void**)&xg,  d_xg);
    cudaGetSymbolAddress((void**)&hs0, d_hseq0);
    cudaGetSymbolAddress((void**)&hs1, d_hseq1);

    cudaFuncSetAttribute(lstm_layer,
                         cudaFuncAttributeMaxDynamicSharedMemorySize,
                         SMEM_BYTES);

    // 1) zero h_0 blocks
    zero_init<<<64, 256>>>(hs0, hs1, BATCH * HIDN);

    // 2) xg for layer 0 (embedding gather fused)
    {
        dim3 grid(G4 / 128, MTOT / 64);
        gemm_tk<<<grid, 256>>>(emb, w_ih0, xg, b_ih0, b_hh0, X,
                               MTOT, G4, HIDN);
    }

    // 3) layer-0 recurrence (persistent)
    zero_bar<<<1, 32>>>();
    lstm_layer<<<64, 256, SMEM_BYTES>>>(xg, hs0, w_hh0);

    // 4) xg for layer 1
    {
        dim3 grid(G4 / 128, MTOT / 64);
        gemm_tk<<<grid, 256>>>(hs0 + (size_t)BATCH * HIDN, w_ih1, xg,
                               b_ih1, b_hh1, nullptr,
                               MTOT, G4, HIDN);
    }

    // 5) layer-1 recurrence (persistent)
    zero_bar<<<1, 32>>>();
    lstm_layer<<<64, 256, SMEM_BYTES>>>(xg, hs1, w_hh1);

    // 6) logits = h_last @ W^T + b
    {
        dim3 grid((NCLS + 127) / 128, BATCH / 64);
        gemm_tk<<<grid, 256>>>(hs1 + (size_t)SEQT * BATCH * HIDN, Wout, out,
                               bout, nullptr, nullptr,
                               BATCH, NCLS, HIDN);
    }
}

// round 4
// speedup vs baseline: 3.8718x; 1.7296x over previous
#include <cuda_runtime.h>
#include <cuda_bf16.h>
#include <cstdint>
#include <cstddef>

// ---------------------------------------------------------------------------
// Problem constants
// ---------------------------------------------------------------------------
#define HIDN   512
#define BATCH  64
#define SEQT   256
#define MTOT   (BATCH * SEQT)       // 16384
#define G4     (4 * HIDN)           // 2048
#define NCLS   50257

// ---------------------------------------------------------------------------
// Static device scratch
// ---------------------------------------------------------------------------
__device__ float d_xg[(size_t)MTOT * G4];
__device__ float d_hseq0[(size_t)(SEQT + 1) * BATCH * HIDN]; // slot 0 = zeros
__device__ float d_hseq1[(size_t)(SEQT + 1) * BATCH * HIDN];
__device__ unsigned d_barrier;

__global__ void zero_init(float* a, float* b, int n)
{
    for (int i = blockIdx.x * blockDim.x + threadIdx.x; i < n;
         i += gridDim.x * blockDim.x) {
        a[i] = 0.0f; b[i] = 0.0f;
    }
}

__global__ void zero_bar()
{
    if (threadIdx.x == 0) d_barrier = 0;
}

// ---------------------------------------------------------------------------
// Common helpers
// ---------------------------------------------------------------------------
__device__ __forceinline__ unsigned f2tf(float f)
{
    unsigned u;
    asm("cvt.rna.tf32.f32 %0, %1;" : "=r"(u) : "f"(f));
    return u;
}

__device__ __forceinline__ void mma_tf32(float* c, unsigned a0, unsigned a1,
                                         unsigned a2, unsigned a3,
                                         unsigned b0, unsigned b1)
{
    asm volatile(
        "mma.sync.aligned.m16n8k8.row.col.f32.tf32.tf32.f32 "
        "{%0,%1,%2,%3}, {%4,%5,%6,%7}, {%8,%9}, {%0,%1,%2,%3};\n"
        : "+f"(c[0]), "+f"(c[1]), "+f"(c[2]), "+f"(c[3])
        : "r"(a0), "r"(a1), "r"(a2), "r"(a3), "r"(b0), "r"(b1));
}

__device__ __forceinline__ float sigm_f(float x)
{
    return 1.0f / (1.0f + __expf(-x));
}

// ---------------------------------------------------------------------------
// tf32 mma GEMM for gate pre-activations:
//   C[m][n] = sum_k A'[m][k] * B[n][k] + bias1[n] + bias2[n]
//   A' = A with optional embedding row gather.
//   Block tile 128(m) x 64(n), 256 threads = 8 warps (4 wm x 2 wn),
//   warp tile 32x32, K chunk 16 (2 mma k-steps).
//   Requires: M mult of 128, N mult of 64, K mult of 16.
// ---------------------------------------------------------------------------
#define GA_STR 20
#define GB_STR 20

__global__ __launch_bounds__(256)
void gemm_mma(const float* __restrict__ A, const float* __restrict__ B,
              float* __restrict__ C,
              const float* __restrict__ bias1, const float* __restrict__ bias2,
              const int* __restrict__ gX,
              int M, int N, int K)
{
    __shared__ unsigned As[128 * GA_STR];   // [m][k] stride 20
    __shared__ unsigned Bs[64 * GB_STR];    // [n][k] stride 20

    const int tid  = threadIdx.x;
    const int lane = tid & 31;
    const int warp = tid >> 5;
    const int wm   = warp >> 1;        // 0..3
    const int wn   = warp & 1;         // 0..1
    const int gid  = lane >> 2;        // 0..7
    const int tig  = lane & 3;         // 0..3
    const int m0   = blockIdx.y * 128;
    const int n0   = blockIdx.x * 64;

    // loader mapping: row = tid>>2 (+64 for second A pass), kq = (tid&3)*4
    const int lrow = tid >> 2;         // 0..63
    const int lkq  = (tid & 3) * 4;    // 0,4,8,12

    const float* Ap[2];
#pragma unroll
    for (int p = 0; p < 2; p++) {
        int m = m0 + p * 64 + lrow;
        long long r;
        if (gX) {
            r = gX[(m & 63) * SEQT + (m >> 6)];
        } else {
            r = m;
        }
        Ap[p] = A + (size_t)r * K + lkq;
    }
    const float* Bp = B + (size_t)(n0 + lrow) * K + lkq;

    float acc[2][4][4];
#pragma unroll
    for (int a = 0; a < 2; a++)
#pragma unroll
        for (int b = 0; b < 4; b++)
#pragma unroll
            for (int c = 0; c < 4; c++) acc[a][b][c] = 0.0f;

    for (int k0 = 0; k0 < K; k0 += 16) {
        float4 av0 = *reinterpret_cast<const float4*>(Ap[0] + k0);
        float4 av1 = *reinterpret_cast<const float4*>(Ap[1] + k0);
        float4 bv  = *reinterpret_cast<const float4*>(Bp + k0);

        __syncthreads();   // previous chunk compute done

        {
            uint4 t0 = make_uint4(f2tf(av0.x), f2tf(av0.y), f2tf(av0.z), f2tf(av0.w));
            uint4 t1 = make_uint4(f2tf(av1.x), f2tf(av1.y), f2tf(av1.z), f2tf(av1.w));
            uint4 tb = make_uint4(f2tf(bv.x),  f2tf(bv.y),  f2tf(bv.z),  f2tf(bv.w));
            *reinterpret_cast<uint4*>(&As[lrow * GA_STR + lkq])        = t0;
            *reinterpret_cast<uint4*>(&As[(64 + lrow) * GA_STR + lkq]) = t1;
            *reinterpret_cast<uint4*>(&Bs[lrow * GB_STR + lkq])        = tb;
        }

        __syncthreads();   // smem ready

#pragma unroll
        for (int kk = 0; kk < 16; kk += 8) {
            unsigned afr[2][4];
#pragma unroll
            for (int mi = 0; mi < 2; mi++) {
                int base = (wm * 32 + mi * 16 + gid) * GA_STR + kk + tig;
                afr[mi][0] = As[base];
                afr[mi][1] = As[base + 8 * GA_STR];
                afr[mi][2] = As[base + 4];
                afr[mi][3] = As[base + 8 * GA_STR + 4];
            }
#pragma unroll
            for (int ni = 0; ni < 4; ni++) {
                int nb = (wn * 32 + ni * 8 + gid) * GB_STR + kk + tig;
                unsigned b0 = Bs[nb];
                unsigned b1 = Bs[nb + 4];
                mma_tf32(acc[0][ni], afr[0][0], afr[0][1], afr[0][2], afr[0][3], b0, b1);
                mma_tf32(acc[1][ni], afr[1][0], afr[1][1], afr[1][2], afr[1][3], b0, b1);
            }
        }
    }

    // epilogue
#pragma unroll
    for (int ni = 0; ni < 4; ni++) {
        int col = n0 + wn * 32 + ni * 8 + 2 * tig;
        float bs0 = bias1[col]     + (bias2 ? bias2[col]     : 0.0f);
        float bs1 = bias1[col + 1] + (bias2 ? bias2[col + 1] : 0.0f);
#pragma unroll
        for (int mi = 0; mi < 2; mi++) {
            int row = m0 + wm * 32 + mi * 16 + gid;
            float2 v0 = make_float2(acc[mi][ni][0] + bs0, acc[mi][ni][1] + bs1);
            float2 v1 = make_float2(acc[mi][ni][2] + bs0, acc[mi][ni][3] + bs1);
            *reinterpret_cast<float2*>(&C[(size_t)row * N + col])       = v0;
            *reinterpret_cast<float2*>(&C[(size_t)(row + 8) * N + col]) = v1;
        }
    }
}

// ---------------------------------------------------------------------------
// fp32 SIMT GEMM (kept for logits: N=50257 not tile-aligned, accuracy-critical)
// ---------------------------------------------------------------------------
__global__ __launch_bounds__(256)
void gemm_tk(const float* __restrict__ A, const float* __restrict__ B,
             float* __restrict__ C,
             const float* __restrict__ bias1,
             int M, int N, int K)
{
    __shared__ float As[16][64];
    __shared__ float Bs[16][132];

    const int tid = threadIdx.x;
    const int m0  = blockIdx.y * 64;
    const int n0  = blockIdx.x * 128;

    const int arow_l = tid >> 2;
    const int akq    = (tid & 3) * 4;
    const float* Aptr = A + (size_t)(m0 + arow_l) * K + akq;

    const float* Bp[2];
    int nlB[2], kqB[2], bval[2];
#pragma unroll
    for (int i = 0; i < 2; i++) {
        int idx = tid + i * 256;
        int nl  = idx >> 2;
        int kq  = (idx & 3) * 4;
        nlB[i]  = nl;
        kqB[i]  = kq;
        bval[i] = (n0 + nl) < N;
        Bp[i]   = B + (size_t)(bval[i] ? (n0 + nl) : 0) * K + kq;
    }

    const int warp = tid >> 5;
    const int lane = tid & 31;
    const int wm = warp >> 2, wn = warp & 3;
    const int lm = lane >> 2, ln = lane & 3;
    const int rm = wm * 32 + lm * 4;
    const int rn = wn * 32 + ln * 8;

    float acc[4][8];
#pragma unroll
    for (int i = 0; i < 4; i++)
#pragma unroll
        for (int j = 0; j < 8; j++) acc[i][j] = 0.0f;

    for (int k0 = 0; k0 < K; k0 += 16) {
        float4 av = *reinterpret_cast<const float4*>(Aptr + k0);
        float4 bv[2];
#pragma unroll
        for (int i = 0; i < 2; i++) {
            if (bval[i]) bv[i] = *reinterpret_cast<const float4*>(Bp[i] + k0);
            else         bv[i] = make_float4(0.f, 0.f, 0.f, 0.f);
        }
        __syncthreads();
        As[akq + 0][arow_l] = av.x;
        As[akq + 1][arow_l] = av.y;
        As[akq + 2][arow_l] = av.z;
        As[akq + 3][arow_l] = av.w;
#pragma unroll
        for (int i = 0; i < 2; i++) {
            Bs[kqB[i] + 0][nlB[i]] = bv[i].x;
            Bs[kqB[i] + 1][nlB[i]] = bv[i].y;
            Bs[kqB[i] + 2][nlB[i]] = bv[i].z;
            Bs[kqB[i] + 3][nlB[i]] = bv[i].w;
        }
        __syncthreads();
#pragma unroll
        for (int kk = 0; kk < 16; kk++) {
            float a4[4], b8[8];
            *reinterpret_cast<float4*>(a4)     = *reinterpret_cast<const float4*>(&As[kk][rm]);
            *reinterpret_cast<float4*>(b8)     = *reinterpret_cast<const float4*>(&Bs[kk][rn]);
            *reinterpret_cast<float4*>(b8 + 4) = *reinterpret_cast<const float4*>(&Bs[kk][rn + 4]);
#pragma unroll
            for (int i = 0; i < 4; i++)
#pragma unroll
                for (int j = 0; j < 8; j++)
                    acc[i][j] += a4[i] * b8[j];
        }
    }

#pragma unroll
    for (int j = 0; j < 8; j++) {
        int n = n0 + rn + j;
        if (n < N) {
            float bsum = bias1[n];
#pragma unroll
            for (int i = 0; i < 4; i++)
                C[(size_t)(m0 + rm + i) * N + n] = acc[i][j] + bsum;
        }
    }
}

// ---------------------------------------------------------------------------
// Persistent LSTM layer kernel (tf32 mma, 512 threads, 2-way k-split)
//
// Grid: 64 blocks x 512 threads. Block blk owns hidden units [blk*8, blk*8+8)
// -> 32 gate columns. 16 warps: ks = warp>>3 (k half), wm = (warp&7)>>1
// (batch 16-row tile), wn = warp&1 (gate-column pair).
// ---------------------------------------------------------------------------
#define HS_STRIDE 516
#define CS_STRIDE 68
#define GS_STRIDE 65
#define GHALF     (32 * GS_STRIDE)           // 2080 floats per k-half
#define WS_OFF    (64 * HS_STRIDE)           // 33024
#define CS_OFF    (WS_OFF + 32 * HS_STRIDE)  // 49536
#define SMEM_FLOATS (CS_OFF + 8 * CS_STRIDE) // 50080
#define SMEM_BYTES  (SMEM_FLOATS * 4)        // 200320 B

__global__ __launch_bounds__(512)
void lstm_layer(const float* __restrict__ xg,     // [256][64][2048]
                float* __restrict__ hseq,         // [257][64][512], slot0 = 0
                const float* __restrict__ w_hh)   // [2048][512]
{
    extern __shared__ float sm[];
    float* h_s = sm;                 // 64 x 512, stride 516
    float* w_s = sm + WS_OFF;        // 32 x 512, stride 516 (tf32)
    float* c_s = sm + CS_OFF;        // 8 x 64, stride 68
    float* g_s = sm;                 // alias of h_s: 2 x 32 x 64, stride 65

    const int tid  = threadIdx.x;
    const int blk  = blockIdx.x;     // 0..63
    const int lane = tid & 31;
    const int warp = tid >> 5;       // 0..15
    const int ks   = warp >> 3;      // 0..1 (k half)
    const int wm   = (warp & 7) >> 1;// 0..3
    const int wn   = warp & 1;       // 0..1
    const int gid  = lane >> 2;      // 0..7
    const int tig  = lane & 3;       // 0..3

    // ---- preload w tile as tf32 (once) -----------------------------------
#pragma unroll
    for (int i = 0; i < 8; i++) {
        int idx = tid + i * 512;     // 0..4095 float4 slots
        int r   = idx >> 7;          // 0..31
        int q4  = (idx & 127) * 4;
        int grow = (r >> 3) * 512 + blk * 8 + (r & 7);
        float4 v = *reinterpret_cast<const float4*>(w_hh + (size_t)grow * 512 + q4);
        unsigned* dst = reinterpret_cast<unsigned*>(w_s + r * HS_STRIDE + q4);
        dst[0] = f2tf(v.x); dst[1] = f2tf(v.y);
        dst[2] = f2tf(v.z); dst[3] = f2tf(v.w);
    }
    for (int i = tid; i < 8 * CS_STRIDE; i += 512) c_s[i] = 0.0f;
    __syncthreads();

    // fragment base pointers
    const int koff = ks * 256;
    const float* pa  = h_s + (wm * 16 + gid) * HS_STRIDE + tig + koff;
    const float* pa8 = pa + 8 * HS_STRIDE;
    const float* pb0 = w_s + ((wn * 2 + 0) * 8 + gid) * HS_STRIDE + tig + koff;
    const float* pb1 = w_s + ((wn * 2 + 1) * 8 + gid) * HS_STRIDE + tig + koff;

    // epilogue mapping: one (b, unit) pair per thread
    const int eb   = tid >> 3;       // 0..63
    const int eul  = tid & 7;        // 0..7
    const int ucol = blk * 8 + eul;

    for (int t = 0; t < SEQT; t++) {
        // ---- prefetch xg for this step (consumed in epilogue) -------------
        const float* xgb = xg + (size_t)t * (BATCH * G4) + (size_t)eb * G4;
        float px0 = xgb[ucol];
        float px1 = xgb[512  + ucol];
        float px2 = xgb[1024 + ucol];
        float px3 = xgb[1536 + ucol];

        // ---- stage h_{t} into SMEM ----------------------------------------
        const float* hp = hseq + (size_t)t * (BATCH * HIDN);
#pragma unroll
        for (int i = 0; i < 16; i++) {
            int idx = tid + i * 512;     // 0..8191
            int b   = idx >> 7;          // 0..63
            int q4  = (idx & 127) * 4;
            float4 v = *reinterpret_cast<const float4*>(hp + b * 512 + q4);
            *reinterpret_cast<float4*>(h_s + b * HS_STRIDE + q4) = v;
        }
        __syncthreads();

        // ---- k-loop: 32 iters (k half), 2 mmas each -----------------------
        float acc0[4] = {0.f, 0.f, 0.f, 0.f};
        float acc1[4] = {0.f, 0.f, 0.f, 0.f};
#pragma unroll 8
        for (int k0 = 0; k0 < 256; k0 += 8) {
            unsigned a0 = __float_as_uint(pa [k0]);
            unsigned a1 = __float_as_uint(pa8[k0]);
            unsigned a2 = __float_as_uint(pa [k0 + 4]);
            unsigned a3 = __float_as_uint(pa8[k0 + 4]);
            unsigned b00 = __float_as_uint(pb0[k0]);
            unsigned b01 = __float_as_uint(pb0[k0 + 4]);
            unsigned b10 = __float_as_uint(pb1[k0]);
            unsigned b11 = __float_as_uint(pb1[k0 + 4]);
            mma_tf32(acc0, a0, a1, a2, a3, b00, b01);
            mma_tf32(acc1, a0, a1, a2, a3, b10, b11);
        }
        __syncthreads();   // h_s reads done; g_s alias writable

        // ---- stage partial C frags into g_s[ks half] -----------------------
        {
            float* gh = g_s + ks * GHALF;
            int b  = wm * 16 + gid;
            int g0 = wn * 2 + 0;
            int g1 = wn * 2 + 1;
            int u0 = 2 * tig;
            gh[(g0 * 8 + u0    ) * GS_STRIDE + b    ] = acc0[0];
            gh[(g0 * 8 + u0 + 1) * GS_STRIDE + b    ] = acc0[1];
            gh[(g0 * 8 + u0    ) * GS_STRIDE + b + 8] = acc0[2];
            gh[(g0 * 8 + u0 + 1) * GS_STRIDE + b + 8] = acc0[3];
            gh[(g1 * 8 + u0    ) * GS_STRIDE + b    ] = acc1[0];
            gh[(g1 * 8 + u0 + 1) * GS_STRIDE + b    ] = acc1[1];
            gh[(g1 * 8 + u0    ) * GS_STRIDE + b + 8] = acc1[2];
            gh[(g1 * 8 + u0 + 1) * GS_STRIDE + b + 8] = acc1[3];
        }
        __syncthreads();

        // ---- gates + cell update: one (b, u) pair per thread ----------------
        float* hout = hseq + (size_t)(t + 1) * (BATCH * HIDN);
        {
            float gi = g_s[( 0 + eul) * GS_STRIDE + eb] + g_s[GHALF + ( 0 + eul) * GS_STRIDE + eb] + px0;
            float gf = g_s[( 8 + eul) * GS_STRIDE + eb] + g_s[GHALF + ( 8 + eul) * GS_STRIDE + eb] + px1;
            float gg = g_s[(16 + eul) * GS_STRIDE + eb] + g_s[GHALF + (16 + eul) * GS_STRIDE + eb] + px2;
            float go = g_s[(24 + eul) * GS_STRIDE + eb] + g_s[GHALF + (24 + eul) * GS_STRIDE + eb] + px3;

            float i_t = sigm_f(gi);
            float f_t = sigm_f(gf);
            float g_t = tanhf(gg);
            float o_t = sigm_f(go);

            float cn = f_t * c_s[eul * CS_STRIDE + eb] + i_t * g_t;
            c_s[eul * CS_STRIDE + eb] = cn;
            float hv = o_t * tanhf(cn);
            hout[eb * 512 + ucol] = __uint_as_float(f2tf(hv));
        }

        // ---- grid barrier ----------------------------------------------------
        if (tid == 0) {
            unsigned* bar = &d_barrier;
            asm volatile("red.release.gpu.global.add.u32 [%0], %1;"
                         :: "l"(bar), "r"(1u) : "memory");
            unsigned target = 64u * (unsigned)(t + 1);
            unsigned v;
            do {
                asm volatile("ld.acquire.gpu.global.u32 %0, [%1];"
                             : "=r"(v) : "l"(bar) : "memory");
            } while (v < target);
        }
        __syncthreads();
    }
}

// ---------------------------------------------------------------------------
// kernel_launch
// ---------------------------------------------------------------------------
extern "C" void kernel_launch(void* const* d_in, const int* in_sizes, int n_in,
                              void* d_out, int out_size)
{
    const int*   X     = (const int*)  d_in[0];
    const float* emb   = (const float*)d_in[1];
    const float* w_ih0 = (const float*)d_in[2];
    const float* w_hh0 = (const float*)d_in[3];
    const float* b_ih0 = (const float*)d_in[4];
    const float* b_hh0 = (const float*)d_in[5];
    const float* w_ih1 = (const float*)d_in[6];
    const float* w_hh1 = (const float*)d_in[7];
    const float* b_ih1 = (const float*)d_in[8];
    const float* b_hh1 = (const float*)d_in[9];
    const float* Wout  = (const float*)d_in[10];
    const float* bout  = (const float*)d_in[11];
    float* out = (float*)d_out;

    float *xg, *hs0, *hs1;
    cudaGetSymbolAddress((void**)&xg,  d_xg);
    cudaGetSymbolAddress((void**)&hs0, d_hseq0);
    cudaGetSymbolAddress((void**)&hs1, d_hseq1);

    cudaFuncSetAttribute(lstm_layer,
                         cudaFuncAttributeMaxDynamicSharedMemorySize,
                         SMEM_BYTES);

    // 1) zero h_0 blocks
    zero_init<<<64, 256>>>(hs0, hs1, BATCH * HIDN);

    // 2) xg for layer 0 (embedding gather fused, tf32 mma)
    {
        dim3 grid(G4 / 64, MTOT / 128);
        gemm_mma<<<grid, 256>>>(emb, w_ih0, xg, b_ih0, b_hh0, X,
                                MTOT, G4, HIDN);
    }

    // 3) layer-0 recurrence (persistent)
    zero_bar<<<1, 32>>>();
    lstm_layer<<<64, 512, SMEM_BYTES>>>(xg, hs0, w_hh0);

    // 4) xg for layer 1 (tf32 mma)
    {
        dim3 grid(G4 / 64, MTOT / 128);
        gemm_mma<<<grid, 256>>>(hs0 + (size_t)BATCH * HIDN, w_ih1, xg,
                                b_ih1, b_hh1, nullptr,
                                MTOT, G4, HIDN);
    }

    // 5) layer-1 recurrence (persistent)
    zero_bar<<<1, 32>>>();
    lstm_layer<<<64, 512, SMEM_BYTES>>>(xg, hs1, w_hh1);

    // 6) logits = h_last @ W^T + b  (fp32, accuracy-critical, cheap)
    {
        dim3 grid((NCLS + 127) / 128, BATCH / 64);
        gemm_tk<<<grid, 256>>>(hs1 + (size_t)SEQT * BATCH * HIDN, Wout, out,
                               bout, BATCH, NCLS, HIDN);
    }
}

// round 5
// speedup vs baseline: 7.7937x; 2.0130x over previous
#include <cuda_runtime.h>
#include <cuda_fp16.h>
#include <cstdint>
#include <cstddef>

// ---------------------------------------------------------------------------
// Problem constants
// ---------------------------------------------------------------------------
#define HIDN   512
#define BATCH  64
#define SEQT   256
#define MTOT   (BATCH * SEQT)       // 16384
#define G4     (4 * HIDN)           // 2048
#define NCLS   50257
#define SEQH   (BATCH * HIDN)       // 32768

// ---------------------------------------------------------------------------
// Static device scratch
// ---------------------------------------------------------------------------
__device__ float  d_xg[(size_t)MTOT * G4];               // layer-0 gate preacts
__device__ __half d_h0seq[(size_t)(SEQT + 1) * SEQH];    // slot 0 = zeros
__device__ __half d_h1seq[(size_t)(SEQT + 1) * SEQH];
__device__ float  d_hlast[SEQH];                         // h1[255] fp32
__device__ unsigned d_bars[64];                          // [0]=bar0, [32]=bar1

__global__ void zero_h(__half* a, __half* b, int n)
{
    for (int i = blockIdx.x * blockDim.x + threadIdx.x; i < n;
         i += gridDim.x * blockDim.x) {
        a[i] = __float2half(0.0f);
        b[i] = __float2half(0.0f);
    }
}

__global__ void zero_bar()
{
    if (threadIdx.x == 0) { d_bars[0] = 0; d_bars[32] = 0; }
}

// ---------------------------------------------------------------------------
// Common helpers
// ---------------------------------------------------------------------------
__device__ __forceinline__ unsigned f2tf(float f)
{
    unsigned u;
    asm("cvt.rna.tf32.f32 %0, %1;" : "=r"(u) : "f"(f));
    return u;
}

__device__ __forceinline__ void mma_tf32(float* c, unsigned a0, unsigned a1,
                                         unsigned a2, unsigned a3,
                                         unsigned b0, unsigned b1)
{
    asm volatile(
        "mma.sync.aligned.m16n8k8.row.col.f32.tf32.tf32.f32 "
        "{%0,%1,%2,%3}, {%4,%5,%6,%7}, {%8,%9}, {%0,%1,%2,%3};\n"
        : "+f"(c[0]), "+f"(c[1]), "+f"(c[2]), "+f"(c[3])
        : "r"(a0), "r"(a1), "r"(a2), "r"(a3), "r"(b0), "r"(b1));
}

#define LDSM4(r0, r1, r2, r3, addr)                                        \
    asm volatile("ldmatrix.sync.aligned.m8n8.x4.shared.b16 "               \
                 "{%0,%1,%2,%3}, [%4];"                                    \
                 : "=r"(r0), "=r"(r1), "=r"(r2), "=r"(r3) : "r"(addr))

#define MMA16816(c, a0, a1, a2, a3, b0, b1)                                \
    asm volatile("mma.sync.aligned.m16n8k16.row.col.f32.f16.f16.f32 "      \
                 "{%0,%1,%2,%3}, {%4,%5,%6,%7}, {%8,%9}, {%0,%1,%2,%3};"   \
                 : "+f"((c)[0]), "+f"((c)[1]), "+f"((c)[2]), "+f"((c)[3])  \
                 : "r"(a0), "r"(a1), "r"(a2), "r"(a3), "r"(b0), "r"(b1))

__device__ __forceinline__ float sigm_f(float x)
{
    return 1.0f / (1.0f + __expf(-x));
}

// ---------------------------------------------------------------------------
// tf32 mma GEMM for layer-0 gate pre-activations (with embedding gather)
//   C[m][n] = sum_k A'[m][k]*B[n][k] + bias1[n] + bias2[n]
//   Block 128(m) x 64(n), 256 threads, warp tile 32x32.
// ---------------------------------------------------------------------------
#define GA_STR 20
#define GB_STR 20

__global__ __launch_bounds__(256)
void gemm_mma(const float* __restrict__ A, const float* __restrict__ B,
              float* __restrict__ C,
              const float* __restrict__ bias1, const float* __restrict__ bias2,
              const int* __restrict__ gX,
              int M, int N, int K)
{
    __shared__ unsigned As[128 * GA_STR];
    __shared__ unsigned Bs[64 * GB_STR];

    const int tid  = threadIdx.x;
    const int lane = tid & 31;
    const int warp = tid >> 5;
    const int wm   = warp >> 1;
    const int wn   = warp & 1;
    const int gid  = lane >> 2;
    const int tig  = lane & 3;
    const int m0   = blockIdx.y * 128;
    const int n0   = blockIdx.x * 64;

    const int lrow = tid >> 2;
    const int lkq  = (tid & 3) * 4;

    const float* Ap[2];
#pragma unroll
    for (int p = 0; p < 2; p++) {
        int m = m0 + p * 64 + lrow;
        long long r;
        if (gX) r = gX[(m & 63) * SEQT + (m >> 6)];
        else    r = m;
        Ap[p] = A + (size_t)r * K + lkq;
    }
    const float* Bp = B + (size_t)(n0 + lrow) * K + lkq;

    float acc[2][4][4];
#pragma unroll
    for (int a = 0; a < 2; a++)
#pragma unroll
        for (int b = 0; b < 4; b++)
#pragma unroll
            for (int c = 0; c < 4; c++) acc[a][b][c] = 0.0f;

    for (int k0 = 0; k0 < K; k0 += 16) {
        float4 av0 = *reinterpret_cast<const float4*>(Ap[0] + k0);
        float4 av1 = *reinterpret_cast<const float4*>(Ap[1] + k0);
        float4 bv  = *reinterpret_cast<const float4*>(Bp + k0);

        __syncthreads();
        {
            uint4 t0 = make_uint4(f2tf(av0.x), f2tf(av0.y), f2tf(av0.z), f2tf(av0.w));
            uint4 t1 = make_uint4(f2tf(av1.x), f2tf(av1.y), f2tf(av1.z), f2tf(av1.w));
            uint4 tb = make_uint4(f2tf(bv.x),  f2tf(bv.y),  f2tf(bv.z),  f2tf(bv.w));
            *reinterpret_cast<uint4*>(&As[lrow * GA_STR + lkq])        = t0;
            *reinterpret_cast<uint4*>(&As[(64 + lrow) * GA_STR + lkq]) = t1;
            *reinterpret_cast<uint4*>(&Bs[lrow * GB_STR + lkq])        = tb;
        }
        __syncthreads();

#pragma unroll
        for (int kk = 0; kk < 16; kk += 8) {
            unsigned afr[2][4];
#pragma unroll
            for (int mi = 0; mi < 2; mi++) {
                int base = (wm * 32 + mi * 16 + gid) * GA_STR + kk + tig;
                afr[mi][0] = As[base];
                afr[mi][1] = As[base + 8 * GA_STR];
                afr[mi][2] = As[base + 4];
                afr[mi][3] = As[base + 8 * GA_STR + 4];
            }
#pragma unroll
            for (int ni = 0; ni < 4; ni++) {
                int nb = (wn * 32 + ni * 8 + gid) * GB_STR + kk + tig;
                unsigned b0 = Bs[nb];
                unsigned b1 = Bs[nb + 4];
                mma_tf32(acc[0][ni], afr[0][0], afr[0][1], afr[0][2], afr[0][3], b0, b1);
                mma_tf32(acc[1][ni], afr[1][0], afr[1][1], afr[1][2], afr[1][3], b0, b1);
            }
        }
    }

#pragma unroll
    for (int ni = 0; ni < 4; ni++) {
        int col = n0 + wn * 32 + ni * 8 + 2 * tig;
        float bs0 = bias1[col]     + (bias2 ? bias2[col]     : 0.0f);
        float bs1 = bias1[col + 1] + (bias2 ? bias2[col + 1] : 0.0f);
#pragma unroll
        for (int mi = 0; mi < 2; mi++) {
            int row = m0 + wm * 32 + mi * 16 + gid;
            float2 v0 = make_float2(acc[mi][ni][0] + bs0, acc[mi][ni][1] + bs1);
            float2 v1 = make_float2(acc[mi][ni][2] + bs0, acc[mi][ni][3] + bs1);
            *reinterpret_cast<float2*>(&C[(size_t)row * N + col])       = v0;
            *reinterpret_cast<float2*>(&C[(size_t)(row + 8) * N + col]) = v1;
        }
    }
}

// ---------------------------------------------------------------------------
// fp32 SIMT GEMM (logits: N=50257, accuracy-critical, cheap)
// ---------------------------------------------------------------------------
__global__ __launch_bounds__(256)
void gemm_tk(const float* __restrict__ A, const float* __restrict__ B,
             float* __restrict__ C,
             const float* __restrict__ bias1,
             int M, int N, int K)
{
    __shared__ float As[16][64];
    __shared__ float Bs[16][132];

    const int tid = threadIdx.x;
    const int m0  = blockIdx.y * 64;
    const int n0  = blockIdx.x * 128;

    const int arow_l = tid >> 2;
    const int akq    = (tid & 3) * 4;
    const float* Aptr = A + (size_t)(m0 + arow_l) * K + akq;

    const float* Bp[2];
    int nlB[2], kqB[2], bval[2];
#pragma unroll
    for (int i = 0; i < 2; i++) {
        int idx = tid + i * 256;
        int nl  = idx >> 2;
        int kq  = (idx & 3) * 4;
        nlB[i]  = nl;
        kqB[i]  = kq;
        bval[i] = (n0 + nl) < N;
        Bp[i]   = B + (size_t)(bval[i] ? (n0 + nl) : 0) * K + kq;
    }

    const int warp = tid >> 5;
    const int lane = tid & 31;
    const int wm = warp >> 2, wn = warp & 3;
    const int lm = lane >> 2, ln = lane & 3;
    const int rm = wm * 32 + lm * 4;
    const int rn = wn * 32 + ln * 8;

    float acc[4][8];
#pragma unroll
    for (int i = 0; i < 4; i++)
#pragma unroll
        for (int j = 0; j < 8; j++) acc[i][j] = 0.0f;

    for (int k0 = 0; k0 < K; k0 += 16) {
        float4 av = *reinterpret_cast<const float4*>(Aptr + k0);
        float4 bv[2];
#pragma unroll
        for (int i = 0; i < 2; i++) {
            if (bval[i]) bv[i] = *reinterpret_cast<const float4*>(Bp[i] + k0);
            else         bv[i] = make_float4(0.f, 0.f, 0.f, 0.f);
        }
        __syncthreads();
        As[akq + 0][arow_l] = av.x;
        As[akq + 1][arow_l] = av.y;
        As[akq + 2][arow_l] = av.z;
        As[akq + 3][arow_l] = av.w;
#pragma unroll
        for (int i = 0; i < 2; i++) {
            Bs[kqB[i] + 0][nlB[i]] = bv[i].x;
            Bs[kqB[i] + 1][nlB[i]] = bv[i].y;
            Bs[kqB[i] + 2][nlB[i]] = bv[i].z;
            Bs[kqB[i] + 3][nlB[i]] = bv[i].w;
        }
        __syncthreads();
#pragma unroll
        for (int kk = 0; kk < 16; kk++) {
            float a4[4], b8[8];
            *reinterpret_cast<float4*>(a4)     = *reinterpret_cast<const float4*>(&As[kk][rm]);
            *reinterpret_cast<float4*>(b8)     = *reinterpret_cast<const float4*>(&Bs[kk][rn]);
            *reinterpret_cast<float4*>(b8 + 4) = *reinterpret_cast<const float4*>(&Bs[kk][rn + 4]);
#pragma unroll
            for (int i = 0; i < 4; i++)
#pragma unroll
                for (int j = 0; j < 8; j++)
                    acc[i][j] += a4[i] * b8[j];
        }
    }

#pragma unroll
    for (int j = 0; j < 8; j++) {
        int n = n0 + rn + j;
        if (n < N) {
            float bsum = bias1[n];
#pragma unroll
            for (int i = 0; i < 4; i++)
                C[(size_t)(m0 + rm + i) * N + n] = acc[i][j] + bsum;
        }
    }
}

// ---------------------------------------------------------------------------
// Pipelined persistent LSTM: 128 blocks.
//   Blocks 0-63  = layer-0 role: k=512, g = h0_{t-1} @ w_hh0^T + xg0[t]
//   Blocks 64-127= layer-1 role: k=1024, g = [h0_t ; h1_{t-1}] @ [w_ih1|w_hh1]^T
//                  + (b_ih1 + b_hh1)
// Block owns 8 hidden units (32 gate columns). fp16 mma m16n8k16, fp32 acc.
// 16 warps: ks=warp>>3 (k half), wm=(warp&7)>>1 (16-batch tile), wn=warp&1
// (16-col tile). Barriers: bar0 (L0 cohort), bar1 (L1 cohort), monotonic.
// ---------------------------------------------------------------------------
#define GH (32 * 65)

__device__ __forceinline__ void bar_red(unsigned* bar)
{
    asm volatile("red.release.gpu.global.add.u32 [%0], %1;"
                 :: "l"(bar), "r"(1u) : "memory");
}

__device__ __forceinline__ void bar_wait(unsigned* bar, unsigned target)
{
    unsigned v;
    do {
        asm volatile("ld.acquire.gpu.global.u32 %0, [%1];"
                     : "=r"(v) : "l"(bar) : "memory");
    } while (v < target);
}

template<int KT, bool IS_L1>
__device__ __forceinline__ void lstm_role(
    const float* __restrict__ xg,      // L0 only
    const float* __restrict__ wA,      // L0: w_hh0 ; L1: w_ih1
    const float* __restrict__ wB,      // L1: w_hh1
    const float* __restrict__ bi,      // L1: b_ih1
    const float* __restrict__ bh,      // L1: b_hh1
    int blk, char* smbase)
{
    constexpr int SH = KT + 8;         // halfs per row (conflict-free LDSM)
    constexpr int NK = KT / 32;        // k16-steps per k-half

    __half* h_s = (__half*)smbase;             // 64 x SH
    __half* w_s = h_s + 64 * SH;               // 32 x SH
    float*  c_s = (float*)(w_s + 32 * SH);     // 8 x 68
    float*  g_s = (float*)smbase;              // alias (2 x 32 x 65)

    const int tid  = threadIdx.x;
    const int lane = tid & 31;
    const int warp = tid >> 5;
    const int ks   = warp >> 3;
    const int wm   = (warp & 7) >> 1;
    const int wn   = warp & 1;

    // ---- preload W as fp16 (resident across all steps) --------------------
#pragma unroll
    for (int i = 0; i < KT / 64; i++) {
        int idx = tid + i * 512;               // 0 .. 32*KT/4-1
        int r   = idx / (KT / 4);              // 0..31
        int kq  = (idx % (KT / 4)) * 4;
        int grow = (r >> 3) * 512 + blk * 8 + (r & 7);
        const float* src;
        if (IS_L1) src = (kq < 512) ? wA + (size_t)grow * 512 + kq
                                    : wB + (size_t)grow * 512 + (kq - 512);
        else       src = wA + (size_t)grow * 512 + kq;
        float4 v = *reinterpret_cast<const float4*>(src);
        __half2* dst = reinterpret_cast<__half2*>(w_s + r * SH + kq);
        dst[0] = __floats2half2_rn(v.x, v.y);
        dst[1] = __floats2half2_rn(v.z, v.w);
    }
    for (int i = tid; i < 8 * 68; i += 512) c_s[i] = 0.0f;

    // epilogue mapping: one (batch, unit) pair per thread
    const int eb   = tid >> 3;
    const int eul  = tid & 7;
    const int ucol = blk * 8 + eul;
    float bia[4] = {0.f, 0.f, 0.f, 0.f};
    if (IS_L1) {
#pragma unroll
        for (int q = 0; q < 4; q++)
            bia[q] = bi[q * 512 + ucol] + bh[q * 512 + ucol];
    }

    // ldmatrix base addresses
    unsigned hbase = (unsigned)__cvta_generic_to_shared(h_s)
                   + (unsigned)((wm * 16 + (lane & 15)) * SH * 2
                                + (ks * (KT / 2) + ((lane >> 4) << 3)) * 2);
    unsigned wbase = (unsigned)__cvta_generic_to_shared(w_s)
                   + (unsigned)((wn * 16 + (lane & 15)) * SH * 2
                                + (ks * (KT / 2) + ((lane >> 4) << 3)) * 2);

    unsigned* bar_self = &d_bars[IS_L1 ? 32 : 0];
    unsigned* bar_dep  = &d_bars[0];
    __half* own = IS_L1 ? d_h1seq : d_h0seq;

    __syncthreads();

    for (int t = 0; t < SEQT; t++) {
        // ---- dependency wait ----------------------------------------------
        if (tid == 0) {
            bar_wait(bar_self, 64u * (unsigned)t);
            if (IS_L1) bar_wait(bar_dep, 64u * (unsigned)(t + 1));
        }
        __syncthreads();

        // ---- prefetch xg (L0) ---------------------------------------------
        float px0 = 0.f, px1 = 0.f, px2 = 0.f, px3 = 0.f;
        if (!IS_L1) {
            const float* xp = xg + (size_t)t * (BATCH * G4) + (size_t)eb * G4;
            px0 = xp[ucol];
            px1 = xp[512  + ucol];
            px2 = xp[1024 + ucol];
            px3 = xp[1536 + ucol];
        }

        // ---- stage h into SMEM (fp16) --------------------------------------
        if (IS_L1) {
            const uint4* s0 = (const uint4*)(d_h0seq + (size_t)(t + 1) * SEQH);
            const uint4* s1 = (const uint4*)(d_h1seq + (size_t)t * SEQH);
#pragma unroll
            for (int i = 0; i < 8; i++) {
                int idx = tid + i * 512;
                int b = idx >> 6, kc = idx & 63;
                uint4 v = s0[b * 64 + kc];
                *reinterpret_cast<uint4*>(h_s + b * SH + kc * 8) = v;
            }
#pragma unroll
            for (int i = 0; i < 8; i++) {
                int idx = tid + i * 512;
                int b = idx >> 6, kc = idx & 63;
                uint4 v = s1[b * 64 + kc];
                *reinterpret_cast<uint4*>(h_s + b * SH + 512 + kc * 8) = v;
            }
        } else {
            const uint4* s0 = (const uint4*)(d_h0seq + (size_t)t * SEQH);
#pragma unroll
            for (int i = 0; i < 8; i++) {
                int idx = tid + i * 512;
                int b = idx >> 6, kc = idx & 63;
                uint4 v = s0[b * 64 + kc];
                *reinterpret_cast<uint4*>(h_s + b * SH + kc * 8) = v;
            }
        }
        __syncthreads();

        // ---- fp16 mma k-loop -----------------------------------------------
        float acc0[4] = {0.f, 0.f, 0.f, 0.f};
        float acc1[4] = {0.f, 0.f, 0.f, 0.f};
#pragma unroll
        for (int kk = 0; kk < NK; kk++) {
            unsigned ra0, ra1, ra2, ra3, rb0, rb1, rb2, rb3;
            LDSM4(ra0, ra1, ra2, ra3, hbase + kk * 32);
            LDSM4(rb0, rb1, rb2, rb3, wbase + kk * 32);
            MMA16816(acc0, ra0, ra1, ra2, ra3, rb0, rb2);
            MMA16816(acc1, ra0, ra1, ra2, ra3, rb1, rb3);
        }
        __syncthreads();   // h_s dead -> g_s alias writable

        // ---- stage C frags: g_s[ks][col 0..31][batch 0..63] ----------------
        {
            float* gh = g_s + ks * GH;
            int b  = wm * 16 + (lane >> 2);
            int c0 = wn * 16 + (lane & 3) * 2;
            int c1 = c0 + 8;
            gh[(c0    ) * 65 + b    ] = acc0[0];
            gh[(c0 + 1) * 65 + b    ] = acc0[1];
            gh[(c0    ) * 65 + b + 8] = acc0[2];
            gh[(c0 + 1) * 65 + b + 8] = acc0[3];
            gh[(c1    ) * 65 + b    ] = acc1[0];
            gh[(c1 + 1) * 65 + b    ] = acc1[1];
            gh[(c1    ) * 65 + b + 8] = acc1[2];
            gh[(c1 + 1) * 65 + b + 8] = acc1[3];
        }
        __syncthreads();

        // ---- gates + cell update -------------------------------------------
        {
            float gi = g_s[( 0 + eul) * 65 + eb] + g_s[GH + ( 0 + eul) * 65 + eb];
            float gf = g_s[( 8 + eul) * 65 + eb] + g_s[GH + ( 8 + eul) * 65 + eb];
            float gg = g_s[(16 + eul) * 65 + eb] + g_s[GH + (16 + eul) * 65 + eb];
            float go = g_s[(24 + eul) * 65 + eb] + g_s[GH + (24 + eul) * 65 + eb];
            if (IS_L1) {
                gi += bia[0]; gf += bia[1]; gg += bia[2]; go += bia[3];
            } else {
                gi += px0; gf += px1; gg += px2; go += px3;
            }

            float i_t = sigm_f(gi);
            float f_t = sigm_f(gf);
            float g_t = tanhf(gg);
            float o_t = sigm_f(go);

            float cn = f_t * c_s[eul * 68 + eb] + i_t * g_t;
            c_s[eul * 68 + eb] = cn;
            float hv = o_t * tanhf(cn);
            own[(size_t)(t + 1) * SEQH + eb * 512 + ucol] = __float2half(hv);
            if (IS_L1 && t == SEQT - 1)
                d_hlast[eb * 512 + ucol] = hv;
        }
        __syncthreads();
        if (tid == 0) bar_red(bar_self);
    }
}

__global__ __launch_bounds__(512)
void lstm_pipeline(const float* __restrict__ xg0,
                   const float* __restrict__ w_hh0,
                   const float* __restrict__ w_ih1,
                   const float* __restrict__ w_hh1,
                   const float* __restrict__ b_ih1,
                   const float* __restrict__ b_hh1)
{
    extern __shared__ char smbase[];
    if (blockIdx.x < 64) {
        lstm_role<512, false>(xg0, w_hh0, nullptr, nullptr, nullptr,
                              blockIdx.x, smbase);
    } else {
        lstm_role<1024, true>(nullptr, w_ih1, w_hh1, b_ih1, b_hh1,
                              blockIdx.x - 64, smbase);
    }
}

// L1 role smem: (64+32)*1032*2 + 8*68*4 = 198144 + 2176
#define PIPE_SMEM (96 * 1032 * 2 + 8 * 68 * 4)

// ---------------------------------------------------------------------------
// kernel_launch
// ---------------------------------------------------------------------------
extern "C" void kernel_launch(void* const* d_in, const int* in_sizes, int n_in,
                              void* d_out, int out_size)
{
    const int*   X     = (const int*)  d_in[0];
    const float* emb   = (const float*)d_in[1];
    const float* w_ih0 = (const float*)d_in[2];
    const float* w_hh0 = (const float*)d_in[3];
    const float* b_ih0 = (const float*)d_in[4];
    const float* b_hh0 = (const float*)d_in[5];
    const float* w_ih1 = (const float*)d_in[6];
    const float* w_hh1 = (const float*)d_in[7];
    const float* b_ih1 = (const float*)d_in[8];
    const float* b_hh1 = (const float*)d_in[9];
    const float* Wout  = (const float*)d_in[10];
    const float* bout  = (const float*)d_in[11];
    float* out = (float*)d_out;

    float *xg, *hlast;
    __half *h0s, *h1s;
    cudaGetSymbolAddress((void**)&xg,    d_xg);
    cudaGetSymbolAddress((void**)&h0s,   d_h0seq);
    cudaGetSymbolAddress((void**)&h1s,   d_h1seq);
    cudaGetSymbolAddress((void**)&hlast, d_hlast);

    cudaFuncSetAttribute(lstm_pipeline,
                         cudaFuncAttributeMaxDynamicSharedMemorySize,
                         PIPE_SMEM);

    // 1) zero h_0 slots + barriers
    zero_h<<<32, 256>>>(h0s, h1s, SEQH);
    zero_bar<<<1, 32>>>();

    // 2) xg for layer 0 (embedding gather fused, tf32 mma)
    {
        dim3 grid(G4 / 64, MTOT / 128);
        gemm_mma<<<grid, 256>>>(emb, w_ih0, xg, b_ih0, b_hh0, X,
                                MTOT, G4, HIDN);
    }

    // 3) pipelined 2-layer recurrence (layer-1 xg fused in-loop)
    lstm_pipeline<<<128, 512, PIPE_SMEM>>>(xg, w_hh0, w_ih1, w_hh1,
                                           b_ih1, b_hh1);

    // 4) logits = h1_last @ W^T + b  (fp32)
    {
        dim3 grid((NCLS + 127) / 128, BATCH / 64);
        gemm_tk<<<grid, 256>>>(hlast, Wout, out, bout, BATCH, NCLS, HIDN);
    }
}

// round 6
// speedup vs baseline: 7.8125x; 1.0024x over previous
#include <cuda_runtime.h>
#include <cuda_fp16.h>
#include <cstdint>
#include <cstddef>

// ---------------------------------------------------------------------------
// Problem constants
// ---------------------------------------------------------------------------
#define HIDN   512
#define BATCH  64
#define SEQT   256
#define MTOT   (BATCH * SEQT)       // 16384
#define G4     (4 * HIDN)           // 2048
#define NCLS   50257
#define SEQH   (BATCH * HIDN)       // 32768

// ---------------------------------------------------------------------------
// Static device scratch
// ---------------------------------------------------------------------------
__device__ float  d_xg[(size_t)MTOT * G4];               // layer-0 gate preacts
__device__ __half d_h0seq[(size_t)(SEQT + 1) * SEQH];    // slot 0 = zeros
__device__ __half d_h1seq[(size_t)(SEQT + 1) * SEQH];
__device__ float  d_hlast[SEQH];                         // h1[255] fp32
__device__ unsigned d_bars[64];                          // [0]=bar0, [32]=bar1

__global__ void zero_h(__half* a, __half* b, int n)
{
    for (int i = blockIdx.x * blockDim.x + threadIdx.x; i < n;
         i += gridDim.x * blockDim.x) {
        a[i] = __float2half(0.0f);
        b[i] = __float2half(0.0f);
    }
}

__global__ void zero_bar()
{
    if (threadIdx.x == 0) { d_bars[0] = 0; d_bars[32] = 0; }
}

// ---------------------------------------------------------------------------
// Common helpers
// ---------------------------------------------------------------------------
__device__ __forceinline__ unsigned f2tf(float f)
{
    unsigned u;
    asm("cvt.rna.tf32.f32 %0, %1;" : "=r"(u) : "f"(f));
    return u;
}

__device__ __forceinline__ void mma_tf32(float* c, unsigned a0, unsigned a1,
                                         unsigned a2, unsigned a3,
                                         unsigned b0, unsigned b1)
{
    asm volatile(
        "mma.sync.aligned.m16n8k8.row.col.f32.tf32.tf32.f32 "
        "{%0,%1,%2,%3}, {%4,%5,%6,%7}, {%8,%9}, {%0,%1,%2,%3};\n"
        : "+f"(c[0]), "+f"(c[1]), "+f"(c[2]), "+f"(c[3])
        : "r"(a0), "r"(a1), "r"(a2), "r"(a3), "r"(b0), "r"(b1));
}

#define LDSM4(r0, r1, r2, r3, addr)                                        \
    asm volatile("ldmatrix.sync.aligned.m8n8.x4.shared.b16 "               \
                 "{%0,%1,%2,%3}, [%4];"                                    \
                 : "=r"(r0), "=r"(r1), "=r"(r2), "=r"(r3) : "r"(addr))

#define MMA16816(c, a0, a1, a2, a3, b0, b1)                                \
    asm volatile("mma.sync.aligned.m16n8k16.row.col.f32.f16.f16.f32 "      \
                 "{%0,%1,%2,%3}, {%4,%5,%6,%7}, {%8,%9}, {%0,%1,%2,%3};"   \
                 : "+f"((c)[0]), "+f"((c)[1]), "+f"((c)[2]), "+f"((c)[3])  \
                 : "r"(a0), "r"(a1), "r"(a2), "r"(a3), "r"(b0), "r"(b1))

__device__ __forceinline__ float sigm_f(float x)
{
    return 1.0f / (1.0f + __expf(-x));
}

// ---------------------------------------------------------------------------
// tf32 mma GEMM, 128x128 tile, 512 threads (16 warps, 4x4), warp tile 32x32.
//   C[m][n] = sum_k A'[m][k]*B[n][k] + bias1[n] (+ bias2[n])
//   Optional embedding row gather on A. Full M/N guards (logits: M=64,
//   N=50257). K multiple of 16.
// ---------------------------------------------------------------------------
__global__ __launch_bounds__(512)
void gemm_mma2(const float* __restrict__ A, const float* __restrict__ B,
               float* __restrict__ C,
               const float* __restrict__ bias1, const float* __restrict__ bias2,
               const int* __restrict__ gX,
               int M, int N, int K)
{
    __shared__ unsigned As[128 * 20];
    __shared__ unsigned Bs[128 * 20];

    const int tid  = threadIdx.x;
    const int lane = tid & 31;
    const int warp = tid >> 5;
    const int wm   = warp >> 2;        // 0..3
    const int wn   = warp & 3;         // 0..3
    const int gid  = lane >> 2;        // 0..7
    const int tig  = lane & 3;         // 0..3
    const int m0   = blockIdx.y * 128;
    const int n0   = blockIdx.x * 128;

    const int lrow = tid >> 2;         // 0..127
    const int lkq  = (tid & 3) * 4;    // 0,4,8,12

    const float* Ap;
    {
        int am = m0 + lrow;
        long long r;
        if (gX)       r = gX[(am & 63) * SEQT + (am >> 6)];
        else if (am < M) r = am;
        else          r = 0;
        Ap = A + (size_t)r * K + lkq;
    }
    const float* Bp;
    {
        int bn = n0 + lrow;
        Bp = B + (size_t)(bn < N ? bn : 0) * K + lkq;
    }

    float acc[2][4][4];
#pragma unroll
    for (int a = 0; a < 2; a++)
#pragma unroll
        for (int b = 0; b < 4; b++)
#pragma unroll
            for (int c = 0; c < 4; c++) acc[a][b][c] = 0.0f;

    for (int k0 = 0; k0 < K; k0 += 16) {
        float4 av = *reinterpret_cast<const float4*>(Ap + k0);
        float4 bv = *reinterpret_cast<const float4*>(Bp + k0);

        __syncthreads();
        {
            uint4 ta = make_uint4(f2tf(av.x), f2tf(av.y), f2tf(av.z), f2tf(av.w));
            uint4 tb = make_uint4(f2tf(bv.x), f2tf(bv.y), f2tf(bv.z), f2tf(bv.w));
            *reinterpret_cast<uint4*>(&As[lrow * 20 + lkq]) = ta;
            *reinterpret_cast<uint4*>(&Bs[lrow * 20 + lkq]) = tb;
        }
        __syncthreads();

#pragma unroll
        for (int kk = 0; kk < 16; kk += 8) {
            unsigned afr[2][4];
#pragma unroll
            for (int mi = 0; mi < 2; mi++) {
                int base = (wm * 32 + mi * 16 + gid) * 20 + kk + tig;
                afr[mi][0] = As[base];
                afr[mi][1] = As[base + 8 * 20];
                afr[mi][2] = As[base + 4];
                afr[mi][3] = As[base + 8 * 20 + 4];
            }
#pragma unroll
            for (int ni = 0; ni < 4; ni++) {
                int nb = (wn * 32 + ni * 8 + gid) * 20 + kk + tig;
                unsigned b0 = Bs[nb];
                unsigned b1 = Bs[nb + 4];
                mma_tf32(acc[0][ni], afr[0][0], afr[0][1], afr[0][2], afr[0][3], b0, b1);
                mma_tf32(acc[1][ni], afr[1][0], afr[1][1], afr[1][2], afr[1][3], b0, b1);
            }
        }
    }

    // guarded epilogue
#pragma unroll
    for (int ni = 0; ni < 4; ni++) {
        int col = n0 + wn * 32 + ni * 8 + 2 * tig;
        float bs0 = 0.f, bs1 = 0.f;
        if (col < N)     bs0 = bias1[col]     + (bias2 ? bias2[col]     : 0.0f);
        if (col + 1 < N) bs1 = bias1[col + 1] + (bias2 ? bias2[col + 1] : 0.0f);
#pragma unroll
        for (int mi = 0; mi < 2; mi++) {
            int row = m0 + wm * 32 + mi * 16 + gid;
#pragma unroll
            for (int rr = 0; rr < 2; rr++) {
                int r = row + rr * 8;
                if (r < M) {
                    if (col < N)
                        C[(size_t)r * N + col]     = acc[mi][ni][rr * 2]     + bs0;
                    if (col + 1 < N)
                        C[(size_t)r * N + col + 1] = acc[mi][ni][rr * 2 + 1] + bs1;
                }
            }
        }
    }
}

// ---------------------------------------------------------------------------
// Pipelined persistent LSTM: 128 blocks.
//   Blocks 0-63  = layer-0: k=512,  g = h0_{t-1} @ w_hh0^T + xg0[t]
//   Blocks 64-127= layer-1: k=1024, g = [h0_t ; h1_{t-1}] @ [w_ih1|w_hh1]^T
//                  + (b_ih1 + b_hh1)
// Block owns 8 hidden units (32 gate columns). fp16 mma m16n8k16, fp32 acc.
// ---------------------------------------------------------------------------
#define GH (32 * 65)

__device__ __forceinline__ void bar_red(unsigned* bar)
{
    asm volatile("red.release.gpu.global.add.u32 [%0], %1;"
                 :: "l"(bar), "r"(1u) : "memory");
}

__device__ __forceinline__ void bar_wait(unsigned* bar, unsigned target)
{
    unsigned v;
    do {
        asm volatile("ld.acquire.gpu.global.u32 %0, [%1];"
                     : "=r"(v) : "l"(bar) : "memory");
    } while (v < target);
}

template<int KT, bool IS_L1>
__device__ __forceinline__ void lstm_role(
    const float* __restrict__ xg,      // L0 only
    const float* __restrict__ wA,      // L0: w_hh0 ; L1: w_ih1
    const float* __restrict__ wB,      // L1: w_hh1
    const float* __restrict__ bi,      // L1: b_ih1
    const float* __restrict__ bh,      // L1: b_hh1
    int blk, char* smbase)
{
    constexpr int SH = KT + 8;         // halfs per row (conflict-free LDSM)
    constexpr int NK = KT / 32;        // k16-steps per k-half

    __half* h_s = (__half*)smbase;                    // 64 x SH
    __half* w_s = h_s + 64 * SH;                      // 32 x SH
    float*  c_s = (float*)(w_s + 32 * SH);            // 8 x 68
    float*  g_s = c_s + 8 * 68;                       // 2 x 32 x 65 (dedicated)

    const int tid  = threadIdx.x;
    const int lane = tid & 31;
    const int warp = tid >> 5;
    const int ks   = warp >> 3;
    const int wm   = (warp & 7) >> 1;
    const int wn   = warp & 1;

    // ---- preload W as fp16 (resident across all steps) --------------------
#pragma unroll
    for (int i = 0; i < KT / 64; i++) {
        int idx = tid + i * 512;               // 0 .. 32*KT/4-1
        int r   = idx / (KT / 4);              // 0..31
        int kq  = (idx % (KT / 4)) * 4;
        int grow = (r >> 3) * 512 + blk * 8 + (r & 7);
        const float* src;
        if (IS_L1) src = (kq < 512) ? wA + (size_t)grow * 512 + kq
                                    : wB + (size_t)grow * 512 + (kq - 512);
        else       src = wA + (size_t)grow * 512 + kq;
        float4 v = *reinterpret_cast<const float4*>(src);
        __half2* dst = reinterpret_cast<__half2*>(w_s + r * SH + kq);
        dst[0] = __floats2half2_rn(v.x, v.y);
        dst[1] = __floats2half2_rn(v.z, v.w);
    }
    for (int i = tid; i < 8 * 68; i += 512) c_s[i] = 0.0f;

    // epilogue mapping: one (batch, unit) pair per thread
    const int eb   = tid >> 3;
    const int eul  = tid & 7;
    const int ucol = blk * 8 + eul;
    float bia[4] = {0.f, 0.f, 0.f, 0.f};
    if (IS_L1) {
#pragma unroll
        for (int q = 0; q < 4; q++)
            bia[q] = bi[q * 512 + ucol] + bh[q * 512 + ucol];
    }

    // ldmatrix base addresses
    unsigned hbase = (unsigned)__cvta_generic_to_shared(h_s)
                   + (unsigned)((wm * 16 + (lane & 15)) * SH * 2
                                + (ks * (KT / 2) + ((lane >> 4) << 3)) * 2);
    unsigned wbase = (unsigned)__cvta_generic_to_shared(w_s)
                   + (unsigned)((wn * 16 + (lane & 15)) * SH * 2
                                + (ks * (KT / 2) + ((lane >> 4) << 3)) * 2);

    unsigned* bar_self = &d_bars[IS_L1 ? 32 : 0];
    unsigned* bar_dep  = &d_bars[0];
    __half* own = IS_L1 ? d_h1seq : d_h0seq;

    __syncthreads();

    for (int t = 0; t < SEQT; t++) {
        // ---- prefetch xg (L0): independent of barriers ---------------------
        float px0 = 0.f, px1 = 0.f, px2 = 0.f, px3 = 0.f;
        if (!IS_L1) {
            const float* xp = xg + (size_t)t * (BATCH * G4) + (size_t)eb * G4;
            px0 = xp[ucol];
            px1 = xp[512  + ucol];
            px2 = xp[1024 + ucol];
            px3 = xp[1536 + ucol];
        }

        // ---- self wait (cheap: own cohort finished step t-1) ----------------
        if (tid == 0) bar_wait(bar_self, 64u * (unsigned)t);
        __syncthreads();

        if (IS_L1) {
            // stage h1[t] (self data) BEFORE the expensive dependency wait,
            // overlapping L0's step-t tail.
            const uint4* s1 = (const uint4*)(d_h1seq + (size_t)t * SEQH);
#pragma unroll
            for (int i = 0; i < 8; i++) {
                int idx = tid + i * 512;
                int b = idx >> 6, kc = idx & 63;
                uint4 v = s1[b * 64 + kc];
                *reinterpret_cast<uint4*>(h_s + b * SH + 512 + kc * 8) = v;
            }
            // dependency wait on layer-0 finishing step t
            if (tid == 0) bar_wait(bar_dep, 64u * (unsigned)(t + 1));
            __syncthreads();
            const uint4* s0 = (const uint4*)(d_h0seq + (size_t)(t + 1) * SEQH);
#pragma unroll
            for (int i = 0; i < 8; i++) {
                int idx = tid + i * 512;
                int b = idx >> 6, kc = idx & 63;
                uint4 v = s0[b * 64 + kc];
                *reinterpret_cast<uint4*>(h_s + b * SH + kc * 8) = v;
            }
        } else {
            const uint4* s0 = (const uint4*)(d_h0seq + (size_t)t * SEQH);
#pragma unroll
            for (int i = 0; i < 8; i++) {
                int idx = tid + i * 512;
                int b = idx >> 6, kc = idx & 63;
                uint4 v = s0[b * 64 + kc];
                *reinterpret_cast<uint4*>(h_s + b * SH + kc * 8) = v;
            }
        }
        __syncthreads();

        // ---- fp16 mma k-loop -----------------------------------------------
        float acc0[4] = {0.f, 0.f, 0.f, 0.f};
        float acc1[4] = {0.f, 0.f, 0.f, 0.f};
#pragma unroll
        for (int kk = 0; kk < NK; kk++) {
            unsigned ra0, ra1, ra2, ra3, rb0, rb1, rb2, rb3;
            LDSM4(ra0, ra1, ra2, ra3, hbase + kk * 32);
            LDSM4(rb0, rb1, rb2, rb3, wbase + kk * 32);
            MMA16816(acc0, ra0, ra1, ra2, ra3, rb0, rb2);
            MMA16816(acc1, ra0, ra1, ra2, ra3, rb1, rb3);
        }

        // ---- stage C frags: g_s[ks][col 0..31][batch 0..63] ----------------
        // (g_s is dedicated storage: no sync needed between mma and stores)
        {
            float* gh = g_s + ks * GH;
            int b  = wm * 16 + (lane >> 2);
            int c0 = wn * 16 + (lane & 3) * 2;
            int c1 = c0 + 8;
            gh[(c0    ) * 65 + b    ] = acc0[0];
            gh[(c0 + 1) * 65 + b    ] = acc0[1];
            gh[(c0    ) * 65 + b + 8] = acc0[2];
            gh[(c0 + 1) * 65 + b + 8] = acc0[3];
            gh[(c1    ) * 65 + b    ] = acc1[0];
            gh[(c1 + 1) * 65 + b    ] = acc1[1];
            gh[(c1    ) * 65 + b + 8] = acc1[2];
            gh[(c1 + 1) * 65 + b + 8] = acc1[3];
        }
        __syncthreads();

        // ---- gates + cell update -------------------------------------------
        {
            float gi = g_s[( 0 + eul) * 65 + eb] + g_s[GH + ( 0 + eul) * 65 + eb];
            float gf = g_s[( 8 + eul) * 65 + eb] + g_s[GH + ( 8 + eul) * 65 + eb];
            float gg = g_s[(16 + eul) * 65 + eb] + g_s[GH + (16 + eul) * 65 + eb];
            float go = g_s[(24 + eul) * 65 + eb] + g_s[GH + (24 + eul) * 65 + eb];
            if (IS_L1) {
                gi += bia[0]; gf += bia[1]; gg += bia[2]; go += bia[3];
            } else {
                gi += px0; gf += px1; gg += px2; go += px3;
            }

            float i_t = sigm_f(gi);
            float f_t = sigm_f(gf);
            float g_t = tanhf(gg);
            float o_t = sigm_f(go);

            float cn = f_t * c_s[eul * 68 + eb] + i_t * g_t;
            c_s[eul * 68 + eb] = cn;
            float hv = o_t * tanhf(cn);
            own[(size_t)(t + 1) * SEQH + eb * 512 + ucol] = __float2half(hv);
            if (IS_L1 && t == SEQT - 1)
                d_hlast[eb * 512 + ucol] = hv;
        }
        __syncthreads();
        if (tid == 0) bar_red(bar_self);
    }
}

__global__ __launch_bounds__(512)
void lstm_pipeline(const float* __restrict__ xg0,
                   const float* __restrict__ w_hh0,
                   const float* __restrict__ w_ih1,
                   const float* __restrict__ w_hh1,
                   const float* __restrict__ b_ih1,
                   const float* __restrict__ b_hh1)
{
    extern __shared__ char smbase[];
    if (blockIdx.x < 64) {
        lstm_role<512, false>(xg0, w_hh0, nullptr, nullptr, nullptr,
                              blockIdx.x, smbase);
    } else {
        lstm_role<1024, true>(nullptr, w_ih1, w_hh1, b_ih1, b_hh1,
                              blockIdx.x - 64, smbase);
    }
}

// L1 role smem: (64+32)*1032*2 + 8*68*4 + 2*32*65*4 = 198144 + 2176 + 16640
#define PIPE_SMEM (96 * 1032 * 2 + 8 * 68 * 4 + 2 * 32 * 65 * 4)

// ---------------------------------------------------------------------------
// kernel_launch
// ---------------------------------------------------------------------------
extern "C" void kernel_launch(void* const* d_in, const int* in_sizes, int n_in,
                              void* d_out, int out_size)
{
    const int*   X     = (const int*)  d_in[0];
    const float* emb   = (const float*)d_in[1];
    const float* w_ih0 = (const float*)d_in[2];
    const float* w_hh0 = (const float*)d_in[3];
    const float* b_ih0 = (const float*)d_in[4];
    const float* b_hh0 = (const float*)d_in[5];
    const float* w_ih1 = (const float*)d_in[6];
    const float* w_hh1 = (const float*)d_in[7];
    const float* b_ih1 = (const float*)d_in[8];
    const float* b_hh1 = (const float*)d_in[9];
    const float* Wout  = (const float*)d_in[10];
    const float* bout  = (const float*)d_in[11];
    float* out = (float*)d_out;

    float *xg, *hlast;
    __half *h0s, *h1s;
    cudaGetSymbolAddress((void**)&xg,    d_xg);
    cudaGetSymbolAddress((void**)&h0s,   d_h0seq);
    cudaGetSymbolAddress((void**)&h1s,   d_h1seq);
    cudaGetSymbolAddress((void**)&hlast, d_hlast);

    cudaFuncSetAttribute(lstm_pipeline,
                         cudaFuncAttributeMaxDynamicSharedMemorySize,
                         PIPE_SMEM);

    // 1) zero h_0 slots + barriers
    zero_h<<<32, 256>>>(h0s, h1s, SEQH);
    zero_bar<<<1, 32>>>();

    // 2) xg for layer 0 (embedding gather fused, tf32 mma, 128x128 tile)
    {
        dim3 grid(G4 / 128, MTOT / 128);
        gemm_mma2<<<grid, 512>>>(emb, w_ih0, xg, b_ih0, b_hh0, X,
                                 MTOT, G4, HIDN);
    }

    // 3) pipelined 2-layer recurrence (layer-1 xg fused in-loop)
    lstm_pipeline<<<128, 512, PIPE_SMEM>>>(xg, w_hh0, w_ih1, w_hh1,
                                           b_ih1, b_hh1);

    // 4) logits = h1_last @ W^T + b  (guarded tf32 mma)
    {
        dim3 grid((NCLS + 127) / 128, 1);
        gemm_mma2<<<grid, 512>>>(hlast, Wout, out, bout, nullptr, nullptr,
                                 BATCH, NCLS, HIDN);
    }
}

// round 7
// speedup vs baseline: 8.0169x; 1.0262x over previous
#include <cuda_runtime.h>
#include <cuda_fp16.h>
#include <cstdint>
#include <cstddef>

// ---------------------------------------------------------------------------
// Problem constants
// ---------------------------------------------------------------------------
#define HIDN   512
#define BATCH  64
#define SEQT   256
#define MTOT   (BATCH * SEQT)       // 16384
#define G4     (4 * HIDN)           // 2048
#define NCLS   50257
#define SEQH   (BATCH * HIDN)       // 32768

// ---------------------------------------------------------------------------
// Static device scratch
// ---------------------------------------------------------------------------
__device__ float  d_xg[(size_t)MTOT * G4];               // layer-0 gate preacts
__device__ __half d_h0seq[(size_t)(SEQT + 1) * SEQH];    // slot 0 = zeros
__device__ __half d_h1seq[(size_t)(SEQT + 1) * SEQH];
__device__ float  d_hlast[SEQH];                         // h1[255] fp32
__device__ unsigned d_bars[64];                          // [0]=bar0, [32]=bar1

__global__ void zero_h(__half* a, __half* b, int n)
{
    for (int i = blockIdx.x * blockDim.x + threadIdx.x; i < n;
         i += gridDim.x * blockDim.x) {
        a[i] = __float2half(0.0f);
        b[i] = __float2half(0.0f);
    }
}

__global__ void zero_bar()
{
    if (threadIdx.x == 0) { d_bars[0] = 0; d_bars[32] = 0; }
}

// ---------------------------------------------------------------------------
// Common helpers
// ---------------------------------------------------------------------------
__device__ __forceinline__ unsigned f2tf(float f)
{
    unsigned u;
    asm("cvt.rna.tf32.f32 %0, %1;" : "=r"(u) : "f"(f));
    return u;
}

__device__ __forceinline__ void mma_tf32(float* c, unsigned a0, unsigned a1,
                                         unsigned a2, unsigned a3,
                                         unsigned b0, unsigned b1)
{
    asm volatile(
        "mma.sync.aligned.m16n8k8.row.col.f32.tf32.tf32.f32 "
        "{%0,%1,%2,%3}, {%4,%5,%6,%7}, {%8,%9}, {%0,%1,%2,%3};\n"
        : "+f"(c[0]), "+f"(c[1]), "+f"(c[2]), "+f"(c[3])
        : "r"(a0), "r"(a1), "r"(a2), "r"(a3), "r"(b0), "r"(b1));
}

#define LDSM4(r0, r1, r2, r3, addr)                                        \
    asm volatile("ldmatrix.sync.aligned.m8n8.x4.shared.b16 "               \
                 "{%0,%1,%2,%3}, [%4];"                                    \
                 : "=r"(r0), "=r"(r1), "=r"(r2), "=r"(r3) : "r"(addr))

#define MMA16816(c, a0, a1, a2, a3, b0, b1)                                \
    asm volatile("mma.sync.aligned.m16n8k16.row.col.f32.f16.f16.f32 "      \
                 "{%0,%1,%2,%3}, {%4,%5,%6,%7}, {%8,%9}, {%0,%1,%2,%3};"   \
                 : "+f"((c)[0]), "+f"((c)[1]), "+f"((c)[2]), "+f"((c)[3])  \
                 : "r"(a0), "r"(a1), "r"(a2), "r"(a3), "r"(b0), "r"(b1))

__device__ __forceinline__ float sigm_f(float x)
{
    return __fdividef(1.0f, 1.0f + __expf(-x));
}

__device__ __forceinline__ float tanh_f(float x)
{
    float e = __expf(2.0f * fabsf(x));
    float r = 1.0f - __fdividef(2.0f, e + 1.0f);
    return copysignf(r, x);
}

// ---------------------------------------------------------------------------
// tf32 mma GEMM, 128x128 tile, 512 threads (16 warps, 4x4), warp tile 32x32.
//   C[m][n] = sum_k A'[m][k]*B[n][k] + bias1[n] (+ bias2[n])
//   Optional embedding row gather on A. Full M/N guards. K multiple of 16.
// ---------------------------------------------------------------------------
__global__ __launch_bounds__(512)
void gemm_mma2(const float* __restrict__ A, const float* __restrict__ B,
               float* __restrict__ C,
               const float* __restrict__ bias1, const float* __restrict__ bias2,
               const int* __restrict__ gX,
               int M, int N, int K)
{
    __shared__ unsigned As[128 * 20];
    __shared__ unsigned Bs[128 * 20];

    const int tid  = threadIdx.x;
    const int lane = tid & 31;
    const int warp = tid >> 5;
    const int wm   = warp >> 2;
    const int wn   = warp & 3;
    const int gid  = lane >> 2;
    const int tig  = lane & 3;
    const int m0   = blockIdx.y * 128;
    const int n0   = blockIdx.x * 128;

    const int lrow = tid >> 2;
    const int lkq  = (tid & 3) * 4;

    const float* Ap;
    {
        int am = m0 + lrow;
        long long r;
        if (gX)          r = gX[(am & 63) * SEQT + (am >> 6)];
        else if (am < M) r = am;
        else             r = 0;
        Ap = A + (size_t)r * K + lkq;
    }
    const float* Bp;
    {
        int bn = n0 + lrow;
        Bp = B + (size_t)(bn < N ? bn : 0) * K + lkq;
    }

    float acc[2][4][4];
#pragma unroll
    for (int a = 0; a < 2; a++)
#pragma unroll
        for (int b = 0; b < 4; b++)
#pragma unroll
            for (int c = 0; c < 4; c++) acc[a][b][c] = 0.0f;

    for (int k0 = 0; k0 < K; k0 += 16) {
        float4 av = *reinterpret_cast<const float4*>(Ap + k0);
        float4 bv = *reinterpret_cast<const float4*>(Bp + k0);

        __syncthreads();
        {
            uint4 ta = make_uint4(f2tf(av.x), f2tf(av.y), f2tf(av.z), f2tf(av.w));
            uint4 tb = make_uint4(f2tf(bv.x), f2tf(bv.y), f2tf(bv.z), f2tf(bv.w));
            *reinterpret_cast<uint4*>(&As[lrow * 20 + lkq]) = ta;
            *reinterpret_cast<uint4*>(&Bs[lrow * 20 + lkq]) = tb;
        }
        __syncthreads();

#pragma unroll
        for (int kk = 0; kk < 16; kk += 8) {
            unsigned afr[2][4];
#pragma unroll
            for (int mi = 0; mi < 2; mi++) {
                int base = (wm * 32 + mi * 16 + gid) * 20 + kk + tig;
                afr[mi][0] = As[base];
                afr[mi][1] = As[base + 8 * 20];
                afr[mi][2] = As[base + 4];
                afr[mi][3] = As[base + 8 * 20 + 4];
            }
#pragma unroll
            for (int ni = 0; ni < 4; ni++) {
                int nb = (wn * 32 + ni * 8 + gid) * 20 + kk + tig;
                unsigned b0 = Bs[nb];
                unsigned b1 = Bs[nb + 4];
                mma_tf32(acc[0][ni], afr[0][0], afr[0][1], afr[0][2], afr[0][3], b0, b1);
                mma_tf32(acc[1][ni], afr[1][0], afr[1][1], afr[1][2], afr[1][3], b0, b1);
            }
        }
    }

#pragma unroll
    for (int ni = 0; ni < 4; ni++) {
        int col = n0 + wn * 32 + ni * 8 + 2 * tig;
        float bs0 = 0.f, bs1 = 0.f;
        if (col < N)     bs0 = bias1[col]     + (bias2 ? bias2[col]     : 0.0f);
        if (col + 1 < N) bs1 = bias1[col + 1] + (bias2 ? bias2[col + 1] : 0.0f);
#pragma unroll
        for (int mi = 0; mi < 2; mi++) {
            int row = m0 + wm * 32 + mi * 16 + gid;
#pragma unroll
            for (int rr = 0; rr < 2; rr++) {
                int r = row + rr * 8;
                if (r < M) {
                    if (col < N)
                        C[(size_t)r * N + col]     = acc[mi][ni][rr * 2]     + bs0;
                    if (col + 1 < N)
                        C[(size_t)r * N + col + 1] = acc[mi][ni][rr * 2 + 1] + bs1;
                }
            }
        }
    }
}

// ---------------------------------------------------------------------------
// Pipelined persistent LSTM, phase-split L1.
//   Blocks 0-63:  layer-0. g = h0_{t-1} @ w_hh0^T + xg0[t]   (k=512)
//   Blocks 64-127: layer-1. g = h1_{t-1} @ w_hh1^T            (phase A,
//                  overlaps L0 producing h0[t]) + h0_t @ w_ih1^T (phase B)
//                  + (b_ih1 + b_hh1)
// Block owns 8 hidden units (32 gate cols). fp16 mma m16n8k16, fp32 acc.
// h staging buffer holds ONE 512-slice (reused across phases in L1).
// ---------------------------------------------------------------------------
#define GH   (32 * 65)
#define SHH  520                       // h buffer stride (halfs)

__device__ __forceinline__ void bar_red(unsigned* bar)
{
    asm volatile("red.release.gpu.global.add.u32 [%0], %1;"
                 :: "l"(bar), "r"(1u) : "memory");
}

__device__ __forceinline__ void bar_wait(unsigned* bar, unsigned target)
{
    unsigned v;
    do {
        asm volatile("ld.acquire.gpu.global.u32 %0, [%1];"
                     : "=r"(v) : "l"(bar) : "memory");
    } while (v < target);
}

// stage one 512-wide fp16 h slice [64][512] -> h_s (stride SHH)
__device__ __forceinline__ void stage_h(__half* h_s, const __half* src, int tid)
{
    const uint4* s = (const uint4*)src;
#pragma unroll
    for (int i = 0; i < 8; i++) {
        int idx = tid + i * 512;
        int b = idx >> 6, kc = idx & 63;
        uint4 v = s[b * 64 + kc];
        *reinterpret_cast<uint4*>(h_s + b * SHH + kc * 8) = v;
    }
}

template<int SW>
__device__ __forceinline__ void mma_phase(float* acc0, float* acc1,
                                          unsigned hbase, unsigned wphase)
{
#pragma unroll
    for (int kk = 0; kk < 16; kk++) {
        unsigned ra0, ra1, ra2, ra3, rb0, rb1, rb2, rb3;
        LDSM4(ra0, ra1, ra2, ra3, hbase + kk * 32);
        LDSM4(rb0, rb1, rb2, rb3, wphase + kk * 32);
        MMA16816(acc0, ra0, ra1, ra2, ra3, rb0, rb2);
        MMA16816(acc1, ra0, ra1, ra2, ra3, rb1, rb3);
    }
}

template<bool IS_L1>
__device__ __forceinline__ void lstm_role(
    const float* __restrict__ xg,      // L0 only
    const float* __restrict__ wA,      // L0: w_hh0 ; L1: w_ih1
    const float* __restrict__ wB,      // L1: w_hh1
    const float* __restrict__ bi,      // L1: b_ih1
    const float* __restrict__ bh,      // L1: b_hh1
    int blk, char* smbase)
{
    constexpr int WKT = IS_L1 ? 1024 : 512;   // weight k extent
    constexpr int SW  = WKT + 8;              // w row stride (halfs)

    __half* h_s = (__half*)smbase;                    // 64 x SHH
    __half* w_s = h_s + 64 * SHH;                     // 32 x SW
    float*  c_s = (float*)(w_s + 32 * SW);            // 8 x 68
    float*  g_s = c_s + 8 * 68;                       // 2 x 32 x 65

    const int tid  = threadIdx.x;
    const int lane = tid & 31;
    const int warp = tid >> 5;
    const int ks   = warp >> 3;        // k half within a 512 slice
    const int wm   = (warp & 7) >> 1;
    const int wn   = warp & 1;

    // ---- preload W as fp16 (resident) -------------------------------------
#pragma unroll
    for (int i = 0; i < WKT / 64; i++) {
        int idx = tid + i * 512;               // 0 .. 32*WKT/4-1
        int r   = idx / (WKT / 4);             // 0..31
        int kq  = (idx % (WKT / 4)) * 4;
        int grow = (r >> 3) * 512 + blk * 8 + (r & 7);
        const float* src;
        if (IS_L1) src = (kq < 512) ? wA + (size_t)grow * 512 + kq
                                    : wB + (size_t)grow * 512 + (kq - 512);
        else       src = wA + (size_t)grow * 512 + kq;
        float4 v = *reinterpret_cast<const float4*>(src);
        __half2* dst = reinterpret_cast<__half2*>(w_s + r * SW + kq);
        dst[0] = __floats2half2_rn(v.x, v.y);
        dst[1] = __floats2half2_rn(v.z, v.w);
    }
    for (int i = tid; i < 8 * 68; i += 512) c_s[i] = 0.0f;

    // epilogue mapping: one (batch, unit) pair per thread
    const int eb   = tid >> 3;
    const int eul  = tid & 7;
    const int ucol = blk * 8 + eul;
    float bia[4] = {0.f, 0.f, 0.f, 0.f};
    if (IS_L1) {
#pragma unroll
        for (int q = 0; q < 4; q++)
            bia[q] = bi[q * 512 + ucol] + bh[q * 512 + ucol];
    }

    // ldmatrix base addresses
    unsigned hbase = (unsigned)__cvta_generic_to_shared(h_s)
                   + (unsigned)(((wm * 16 + (lane & 15)) * SHH
                                 + ks * 256 + ((lane >> 4) << 3)) * 2);
    unsigned wbase = (unsigned)__cvta_generic_to_shared(w_s)
                   + (unsigned)(((wn * 16 + (lane & 15)) * SW
                                 + ks * 256 + ((lane >> 4) << 3)) * 2);

    unsigned* bar0 = &d_bars[0];
    unsigned* bar1 = &d_bars[32];

    __syncthreads();

    for (int t = 0; t < SEQT; t++) {
        float acc0[4] = {0.f, 0.f, 0.f, 0.f};
        float acc1[4] = {0.f, 0.f, 0.f, 0.f};
        float px0 = 0.f, px1 = 0.f, px2 = 0.f, px3 = 0.f;

        if (IS_L1) {
            // ---- self wait (h1[t] ready) + phase A on own data ------------
            if (tid == 0) bar_wait(bar1, 64u * (unsigned)t);
            __syncthreads();
            stage_h(h_s, d_h1seq + (size_t)t * SEQH, tid);
            __syncthreads();
            // phase A: w cols 512..1023 (w_hh1) — overlaps L0's step t
            mma_phase<SW>(acc0, acc1, hbase, wbase + 512 * 2);

            // ---- dependency wait on layer-0 step t -------------------------
            if (tid == 0) bar_wait(bar0, 64u * (unsigned)(t + 1));
            __syncthreads();   // also guarantees phase-A LDSMs done
            stage_h(h_s, d_h0seq + (size_t)(t + 1) * SEQH, tid);
            __syncthreads();
            // phase B: w cols 0..511 (w_ih1)
            mma_phase<SW>(acc0, acc1, hbase, wbase);
        } else {
            // xg prefetch (independent of barrier)
            const float* xp = xg + (size_t)t * (BATCH * G4) + (size_t)eb * G4;
            px0 = xp[ucol];
            px1 = xp[512  + ucol];
            px2 = xp[1024 + ucol];
            px3 = xp[1536 + ucol];

            if (tid == 0) bar_wait(bar0, 64u * (unsigned)t);
            __syncthreads();
            stage_h(h_s, d_h0seq + (size_t)t * SEQH, tid);
            __syncthreads();
            mma_phase<SW>(acc0, acc1, hbase, wbase);
        }

        // ---- stage C frags: g_s[ks][col 0..31][batch 0..63] ----------------
        {
            float* gh = g_s + ks * GH;
            int b  = wm * 16 + (lane >> 2);
            int c0 = wn * 16 + (lane & 3) * 2;
            int c1 = c0 + 8;
            gh[(c0    ) * 65 + b    ] = acc0[0];
            gh[(c0 + 1) * 65 + b    ] = acc0[1];
            gh[(c0    ) * 65 + b + 8] = acc0[2];
            gh[(c0 + 1) * 65 + b + 8] = acc0[3];
            gh[(c1    ) * 65 + b    ] = acc1[0];
            gh[(c1 + 1) * 65 + b    ] = acc1[1];
            gh[(c1    ) * 65 + b + 8] = acc1[2];
            gh[(c1 + 1) * 65 + b + 8] = acc1[3];
        }
        __syncthreads();

        // ---- gates + cell update -------------------------------------------
        {
            float gi = g_s[( 0 + eul) * 65 + eb] + g_s[GH + ( 0 + eul) * 65 + eb];
            float gf = g_s[( 8 + eul) * 65 + eb] + g_s[GH + ( 8 + eul) * 65 + eb];
            float gg = g_s[(16 + eul) * 65 + eb] + g_s[GH + (16 + eul) * 65 + eb];
            float go = g_s[(24 + eul) * 65 + eb] + g_s[GH + (24 + eul) * 65 + eb];
            if (IS_L1) {
                gi += bia[0]; gf += bia[1]; gg += bia[2]; go += bia[3];
            } else {
                gi += px0; gf += px1; gg += px2; go += px3;
            }

            float i_t = sigm_f(gi);
            float f_t = sigm_f(gf);
            float g_t = tanh_f(gg);
            float o_t = sigm_f(go);

            float cn = f_t * c_s[eul * 68 + eb] + i_t * g_t;
            c_s[eul * 68 + eb] = cn;
            float hv = o_t * tanh_f(cn);
            __half* own = IS_L1 ? d_h1seq : d_h0seq;
            own[(size_t)(t + 1) * SEQH + eb * 512 + ucol] = __float2half(hv);
            if (IS_L1 && t == SEQT - 1)
                d_hlast[eb * 512 + ucol] = hv;
        }
        __syncthreads();
        if (tid == 0) bar_red(IS_L1 ? bar1 : bar0);
    }
}

__global__ __launch_bounds__(512)
void lstm_pipeline(const float* __restrict__ xg0,
                   const float* __restrict__ w_hh0,
                   const float* __restrict__ w_ih1,
                   const float* __restrict__ w_hh1,
                   const float* __restrict__ b_ih1,
                   const float* __restrict__ b_hh1)
{
    extern __shared__ char smbase[];
    if (blockIdx.x < 64) {
        lstm_role<false>(xg0, w_hh0, nullptr, nullptr, nullptr,
                         blockIdx.x, smbase);
    } else {
        lstm_role<true>(nullptr, w_ih1, w_hh1, b_ih1, b_hh1,
                        blockIdx.x - 64, smbase);
    }
}

// L1 smem: 64*520*2 + 32*1032*2 + 8*68*4 + 2*32*65*4 = 151424 B
#define PIPE_SMEM (64 * SHH * 2 + 32 * 1032 * 2 + 8 * 68 * 4 + 2 * 32 * 65 * 4)

// ---------------------------------------------------------------------------
// kernel_launch
// ---------------------------------------------------------------------------
extern "C" void kernel_launch(void* const* d_in, const int* in_sizes, int n_in,
                              void* d_out, int out_size)
{
    const int*   X     = (const int*)  d_in[0];
    const float* emb   = (const float*)d_in[1];
    const float* w_ih0 = (const float*)d_in[2];
    const float* w_hh0 = (const float*)d_in[3];
    const float* b_ih0 = (const float*)d_in[4];
    const float* b_hh0 = (const float*)d_in[5];
    const float* w_ih1 = (const float*)d_in[6];
    const float* w_hh1 = (const float*)d_in[7];
    const float* b_ih1 = (const float*)d_in[8];
    const float* b_hh1 = (const float*)d_in[9];
    const float* Wout  = (const float*)d_in[10];
    const float* bout  = (const float*)d_in[11];
    float* out = (float*)d_out;

    float *xg, *hlast;
    __half *h0s, *h1s;
    cudaGetSymbolAddress((void**)&xg,    d_xg);
    cudaGetSymbolAddress((void**)&h0s,   d_h0seq);
    cudaGetSymbolAddress((void**)&h1s,   d_h1seq);
    cudaGetSymbolAddress((void**)&hlast, d_hlast);

    cudaFuncSetAttribute(lstm_pipeline,
                         cudaFuncAttributeMaxDynamicSharedMemorySize,
                         PIPE_SMEM);

    // 1) zero h_0 slots + barriers
    zero_h<<<32, 256>>>(h0s, h1s, SEQH);
    zero_bar<<<1, 32>>>();

    // 2) xg for layer 0 (embedding gather fused, tf32 mma)
    {
        dim3 grid(G4 / 128, MTOT / 128);
        gemm_mma2<<<grid, 512>>>(emb, w_ih0, xg, b_ih0, b_hh0, X,
                                 MTOT, G4, HIDN);
    }

    // 3) pipelined 2-layer recurrence (phase-split L1)
    lstm_pipeline<<<128, 512, PIPE_SMEM>>>(xg, w_hh0, w_ih1, w_hh1,
                                           b_ih1, b_hh1);

    // 4) logits = h1_last @ W^T + b  (guarded tf32 mma)
    {
        dim3 grid((NCLS + 127) / 128, 1);
        gemm_mma2<<<grid, 512>>>(hlast, Wout, out, bout, nullptr, nullptr,
                                 BATCH, NCLS, HIDN);
    }
}